// round 1
// baseline (speedup 1.0000x reference)
#include <cuda_runtime.h>

// Problem dims
constexpr int kB  = 16;
constexpr int kC  = 256;
constexpr int kH  = 64;
constexpr int kW  = 64;
constexpr int kUH = 65;   // FIR output (pad 2,2, 4x4 kernel)
constexpr int kUW = 65;
constexpr int kOC = 256;
constexpr int kOH = 32;
constexpr int kOW = 32;

// Scratch for FIR intermediate u[B][C][65][65]  (~69 MB)
__device__ float g_u[(size_t)kB * kC * kUH * kUW];

typedef unsigned long long ull;

__device__ __forceinline__ ull pack2(float a, float b) {
    ull r;
    asm("mov.b64 %0, {%1, %2};" : "=l"(r) : "f"(a), "f"(b));
    return r;
}
__device__ __forceinline__ void unpack2(ull v, float& a, float& b) {
    asm("mov.b64 {%0, %1}, %2;" : "=f"(a), "=f"(b) : "l"(v));
}
__device__ __forceinline__ void fma2(ull& d, ull a, ull b) {
    // packed f32x2 FMA (Blackwell): d = a*b + d, lanewise
    asm("fma.rn.f32x2 %0, %1, %2, %0;" : "+l"(d) : "l"(a), "l"(b));
}

// ---------------------------------------------------------------------------
// Stage 1: depthwise 4x4 FIR, pad (2,2).  u[i][j] = sum fir[p][q] * x[i+p-2][j+q-2]
// fir = outer([1,3,3,1]) / 64  (symmetric, so conv == xcorr)
// One block per (b,c) plane; plane staged in smem.
// ---------------------------------------------------------------------------
__global__ __launch_bounds__(256) void fir_kernel(const float* __restrict__ x) {
    __shared__ __align__(16) float xs[kH * kW];

    const int bc = blockIdx.x;  // 0 .. B*C-1
    const float* xp = x + (size_t)bc * (kH * kW);
    float* up = g_u + (size_t)bc * (kUH * kUW);

    // Load full 64x64 plane (16 KB) with float4
    const float4* xp4 = (const float4*)xp;
    float4* xs4 = (float4*)xs;
    for (int t = threadIdx.x; t < (kH * kW) / 4; t += 256) xs4[t] = xp4[t];
    __syncthreads();

    const float f1d[4] = {0.125f, 0.375f, 0.375f, 0.125f};

    for (int t = threadIdx.x; t < kUH * kUW; t += 256) {
        const int i = t / kUW;
        const int j = t - i * kUW;
        float acc = 0.0f;
        #pragma unroll
        for (int p = 0; p < 4; p++) {
            const int xi = i + p - 2;
            if (xi < 0 || xi >= kH) continue;
            #pragma unroll
            for (int q = 0; q < 4; q++) {
                const int xj = j + q - 2;
                if (xj < 0 || xj >= kW) continue;
                acc += (f1d[p] * f1d[q]) * xs[xi * kW + xj];
            }
        }
        up[t] = acc;
    }
}

// ---------------------------------------------------------------------------
// Stage 2: 3x3 conv, stride 2, VALID on u -> y[b][oc][32][32], + bias.
// Block: 256 threads computes tile [64 oc][8 m][32 n] for one batch image.
// Thread: 8 oc-pairs (f32x2 lanes) x 4 consecutive n, one m row.
// IC staged through smem in chunks of 4. Packed fma.rn.f32x2 throughout.
// ---------------------------------------------------------------------------
constexpr int ICC = 4;            // input-channel chunk
constexpr int USTR = 67;          // padded smem row stride (2-way conflict max)

__global__ __launch_bounds__(256, 2)
void conv_kernel(const float* __restrict__ wg,
                 const float* __restrict__ bias,
                 float* __restrict__ y) {
    __shared__ __align__(16) float us[ICC * 17 * USTR];      // ~17.9 KB
    __shared__ __align__(16) float ws[ICC * 9 * 64];         //  9.2 KB  [ic][rs][oc]

    const int oc0 = blockIdx.x * 64;
    const int om0 = blockIdx.y * 8;
    const int b   = blockIdx.z;
    const int tid = threadIdx.x;

    const int ocg = tid >> 6;          // 0..3  -> oc sub-range of 16
    const int pos = tid & 63;          // 0..63
    const int mi  = pos >> 3;          // 0..7  output row within tile
    const int n0  = (pos & 7) << 2;    // 0,4,...,28  (4 consecutive n)

    ull acc[8][4];
    #pragma unroll
    for (int t = 0; t < 8; t++)
        #pragma unroll
        for (int nn = 0; nn < 4; nn++) acc[t][nn] = 0ull;

    const float* ub = g_u + (size_t)b * kC * (kUH * kUW);

    for (int ic0 = 0; ic0 < kC; ic0 += ICC) {
        // --- load u patch: ICC x 17 rows x 65 cols ---
        for (int t = tid; t < ICC * 17 * kUW; t += 256) {
            const int icl = t / (17 * kUW);
            const int rem = t - icl * (17 * kUW);
            const int row = rem / kUW;
            const int col = rem - row * kUW;
            us[icl * (17 * USTR) + row * USTR + col] =
                ub[(size_t)(ic0 + icl) * (kUH * kUW) + (2 * om0 + row) * kUW + col];
        }
        // --- load w chunk: [icl][rs][oc] so oc is contiguous (LDS.64 pairs) ---
        for (int t = tid; t < ICC * 9 * 64; t += 256) {
            const int oc  = t / 36;
            const int r36 = t - oc * 36;
            const int icl = r36 / 9;
            const int rs  = r36 - icl * 9;
            ws[icl * (9 * 64) + rs * 64 + oc] =
                wg[((size_t)(oc0 + oc) * kC + ic0 + icl) * 9 + rs];
        }
        __syncthreads();

        #pragma unroll
        for (int icl = 0; icl < ICC; icl++) {
            const float* usp = &us[icl * (17 * USTR)];
            #pragma unroll
            for (int r = 0; r < 3; r++) {
                // 9 consecutive u values cover (4 n) x (3 s): col = 2n+s
                float uu[9];
                const float* urow = usp + (2 * mi + r) * USTR + 2 * n0;
                #pragma unroll
                for (int k = 0; k < 9; k++) uu[k] = urow[k];

                const ull* wrow = (const ull*)&ws[icl * (9 * 64) + (r * 3) * 64];
                #pragma unroll
                for (int s = 0; s < 3; s++) {
                    ull u2[4];
                    #pragma unroll
                    for (int nn = 0; nn < 4; nn++)
                        u2[nn] = pack2(uu[2 * nn + s], uu[2 * nn + s]);
                    #pragma unroll
                    for (int t = 0; t < 8; t++) {
                        const ull wv = wrow[s * 32 + ocg * 8 + t];  // {w[oc],w[oc+1]}
                        #pragma unroll
                        for (int nn = 0; nn < 4; nn++)
                            fma2(acc[t][nn], wv, u2[nn]);
                    }
                }
            }
        }
        __syncthreads();
    }

    // --- epilogue: unpack oc pairs, add bias, vectorized stores ---
    const int om = om0 + mi;
    #pragma unroll
    for (int t = 0; t < 8; t++) {
        const int oc_lo = oc0 + ocg * 16 + 2 * t;
        const float b0 = __ldg(&bias[oc_lo]);
        const float b1 = __ldg(&bias[oc_lo + 1]);
        float l0, h0, l1, h1, l2, h2, l3, h3;
        unpack2(acc[t][0], l0, h0);
        unpack2(acc[t][1], l1, h1);
        unpack2(acc[t][2], l2, h2);
        unpack2(acc[t][3], l3, h3);
        float* yp = y + (((size_t)b * kOC + oc_lo) * kOH + om) * kOW + n0;
        float4 v0 = make_float4(l0 + b0, l1 + b0, l2 + b0, l3 + b0);
        float4 v1 = make_float4(h0 + b1, h1 + b1, h2 + b1, h3 + b1);
        *(float4*)yp = v0;
        *(float4*)(yp + kOH * kOW) = v1;
    }
}

// ---------------------------------------------------------------------------
extern "C" void kernel_launch(void* const* d_in, const int* in_sizes, int n_in,
                              void* d_out, int out_size) {
    (void)in_sizes; (void)n_in; (void)out_size;
    const float* x    = (const float*)d_in[0];
    const float* w    = (const float*)d_in[1];
    const float* bias = (const float*)d_in[2];
    float* y = (float*)d_out;

    fir_kernel<<<kB * kC, 256>>>(x);

    dim3 grid(kOC / 64, kOH / 8, kB);
    conv_kernel<<<grid, 256>>>(w, bias, y);
}

// round 4
// speedup vs baseline: 3.6272x; 3.6272x over previous
#include <cuda_runtime.h>
#include <cstdint>

// ---------------------------------------------------------------------------
// Problem dims
// ---------------------------------------------------------------------------
constexpr int kB = 16, kC = 256, kH = 64, kW = 64;
constexpr int kUH = 65, kUW = 65;
constexpr int kOC = 256, kOH = 32, kOW = 32;

constexpr int KCH = 72;            // 9 rs taps * 8 ic-chunks of 32
constexpr int S   = 3;             // cp.async pipeline stages
constexpr int LDA = 36;            // padded smem stride in floats (conflict-free)
constexpr int TSZ = 128 * LDA * 4; // bytes per 128x32 operand tile (18432)
constexpr int SSZ = 2 * TSZ;       // stage = A tile + B tile
constexpr int SMEM_TOT = S * SSZ;  // 110592 B

// Scratch: u channels-last [b][h][w][c] (tf32-rounded), wt [rs][oc][ic]
__device__ __align__(1024) float g_u[(size_t)kB * kUH * kUW * kC];
__device__ __align__(1024) float g_wt[9 * kOC * kC];

// ---------------------------------------------------------------------------
// Helpers (all sm_80-portable)
// ---------------------------------------------------------------------------
__device__ __forceinline__ uint32_t smem_u32(const void* p) {
    uint32_t a;
    asm("{ .reg .u64 t; cvta.to.shared.u64 t, %1; cvt.u32.u64 %0, t; }"
        : "=r"(a) : "l"(p));
    return a;
}
// round fp32 -> tf32 (round-to-nearest-even mantissa-10) in 32-bit container
__device__ __forceinline__ float to_tf32(float v) {
    uint32_t r;
    asm("cvt.rna.tf32.f32 %0, %1;" : "=r"(r) : "f"(v));
    return __uint_as_float(r);
}
__device__ __forceinline__ void cp16(uint32_t dst, const void* src) {
    asm volatile("cp.async.cg.shared.global [%0], [%1], 16;"
                 :: "r"(dst), "l"(src) : "memory");
}
__device__ __forceinline__ void mma_tf32(float* d, const uint32_t* a,
                                         uint32_t b0, uint32_t b1) {
    asm volatile(
        "mma.sync.aligned.m16n8k8.row.col.f32.tf32.tf32.f32 "
        "{%0,%1,%2,%3}, {%4,%5,%6,%7}, {%8,%9}, {%0,%1,%2,%3};"
        : "+f"(d[0]), "+f"(d[1]), "+f"(d[2]), "+f"(d[3])
        : "r"(a[0]), "r"(a[1]), "r"(a[2]), "r"(a[3]), "r"(b0), "r"(b1));
}

// ---------------------------------------------------------------------------
// Stage 1: separable 4x4 FIR, pad(2,2) -> u[b][h][w][c] channels-last (tf32 RN)
// ---------------------------------------------------------------------------
__global__ __launch_bounds__(256) void fir_kernel(const float* __restrict__ x) {
    __shared__ float vs[64 * 33];
    const int i = blockIdx.x, b = blockIdx.y;
    const int tid = threadIdx.x;
    const int wlane = tid & 63, cg = tid >> 6;
    const float fw[4] = {0.125f, 0.375f, 0.375f, 0.125f};

    for (int c0 = 0; c0 < kC; c0 += 32) {
        #pragma unroll
        for (int k = 0; k < 8; k++) {
            const int c = cg * 8 + k;
            const float* xp = x + ((size_t)(b * kC + c0 + c) * kH) * kW + wlane;
            float acc = 0.f;
            #pragma unroll
            for (int p = 0; p < 4; p++) {
                const int xi = i - 2 + p;
                if (xi >= 0 && xi < kH) acc += fw[p] * xp[xi * kW];
            }
            vs[wlane * 33 + c] = acc;
        }
        __syncthreads();
        for (int idx = tid; idx < kUW * 32; idx += 256) {
            const int wp = idx >> 5, c = idx & 31;
            float acc = 0.f;
            #pragma unroll
            for (int q = 0; q < 4; q++) {
                const int wq = wp - 2 + q;
                if (wq >= 0 && wq < kW) acc += fw[q] * vs[wq * 33 + c];
            }
            g_u[(((size_t)b * kUH + i) * kUW + wp) * kC + c0 + c] = to_tf32(acc);
        }
        __syncthreads();
    }
}

// ---------------------------------------------------------------------------
// Weight transpose: w[oc][ic][rs] -> wt[rs][oc][ic] (tf32 RN)
// ---------------------------------------------------------------------------
__global__ __launch_bounds__(256) void wt_kernel(const float* __restrict__ w) {
    __shared__ float sm[kC * 9];
    const int oc = blockIdx.x;
    for (int idx = threadIdx.x; idx < kC * 9; idx += 256)
        sm[idx] = w[(size_t)oc * kC * 9 + idx];
    __syncthreads();
    for (int idx = threadIdx.x; idx < kC * 9; idx += 256) {
        const int rs = idx >> 8, ic = idx & 255;
        g_wt[((size_t)rs * kOC + oc) * kC + ic] = to_tf32(sm[ic * 9 + rs]);
    }
}

// ---------------------------------------------------------------------------
// Stage 2: implicit-GEMM conv via mma.sync tf32 (m16n8k8).
// CTA: 128(M: 4 oh x 32 ow, one b) x 128(N: oc). 8 warps = 4(M) x 2(N),
// warp tile 32x64 = 2x8 mma tiles. K = 72 chunks of 32, 3-stage cp.async.
// ---------------------------------------------------------------------------
__global__ __launch_bounds__(256, 2)
void conv_mma(const float* __restrict__ bias, float* __restrict__ y) {
    extern __shared__ __align__(16) char smem[];
    const int tid = threadIdx.x, wid = tid >> 5, lane = tid & 31;
    const uint32_t sb = smem_u32(smem);

    const int mtile = blockIdx.x >> 1, ntile = blockIdx.x & 1;
    const int b = mtile >> 3, oh0 = (mtile & 7) << 2, oc0 = ntile << 7;
    const int wm0 = (wid & 3) * 32, wn0 = (wid >> 2) * 64;
    const float* ub = g_u + (size_t)b * kUH * kUW * kC;

    auto load_chunk = [&](int slot, int kc) {
        const int rs = kc >> 3, ic0 = (kc & 7) << 5;
        const int r = rs / 3, s = rs - r * 3;
        const uint32_t abase = sb + slot * SSZ;
        #pragma unroll
        for (int rep = 0; rep < 4; rep++) {
            const int unit = tid + rep * 256;        // 0..1023
            const int mi = unit >> 3, j = unit & 7;
            const int h = 2 * (oh0 + (mi >> 5)) + r;
            const int w = 2 * (mi & 31) + s;
            const float* src = ub + (((size_t)h * kUW + w) << 8) + ic0 + (j << 2);
            cp16(abase + mi * (LDA * 4) + j * 16, src);
        }
        const uint32_t bbase = abase + TSZ;
        const float* wsrc = g_wt + ((size_t)rs << 16) + ((size_t)oc0 << 8) + ic0;
        #pragma unroll
        for (int rep = 0; rep < 4; rep++) {
            const int unit = tid + rep * 256;        // 0..1023
            const int n = unit >> 3, j = unit & 7;
            cp16(bbase + n * (LDA * 4) + j * 16, wsrc + ((size_t)n << 8) + (j << 2));
        }
    };

    load_chunk(0, 0);
    asm volatile("cp.async.commit_group;" ::: "memory");
    load_chunk(1, 1);
    asm volatile("cp.async.commit_group;" ::: "memory");

    float acc[2][8][4];
    #pragma unroll
    for (int mt = 0; mt < 2; mt++)
        #pragma unroll
        for (int nt = 0; nt < 8; nt++)
            #pragma unroll
            for (int v = 0; v < 4; v++) acc[mt][nt][v] = 0.f;

    const int r0 = lane >> 2, c0l = lane & 3;

    for (int i = 0; i < KCH; i++) {
        asm volatile("cp.async.wait_group 1;" ::: "memory");
        __syncthreads();

        // prefetch chunk i+2 into slot (i+2)%S == (i-1)%S (safe: compute(i-1) done)
        if (i + 2 < KCH) load_chunk((i + 2) % S, i + 2);
        asm volatile("cp.async.commit_group;" ::: "memory");

        const float* As = (const float*)(smem + (i % S) * SSZ);
        const float* Bs = As + 128 * LDA;

        #pragma unroll
        for (int kk = 0; kk < 4; kk++) {
            const int k0 = kk * 8;
            uint32_t a[2][4];
            #pragma unroll
            for (int mt = 0; mt < 2; mt++) {
                const float* ap = As + (wm0 + mt * 16 + r0) * LDA + k0 + c0l;
                a[mt][0] = __float_as_uint(ap[0]);
                a[mt][1] = __float_as_uint(ap[8 * LDA]);
                a[mt][2] = __float_as_uint(ap[4]);
                a[mt][3] = __float_as_uint(ap[8 * LDA + 4]);
            }
            #pragma unroll
            for (int nt = 0; nt < 8; nt++) {
                const float* bp = Bs + (wn0 + nt * 8 + r0) * LDA + k0 + c0l;
                const uint32_t b0 = __float_as_uint(bp[0]);
                const uint32_t b1 = __float_as_uint(bp[4]);
                mma_tf32(acc[0][nt], a[0], b0, b1);
                mma_tf32(acc[1][nt], a[1], b0, b1);
            }
        }
    }

    // --- epilogue: transpose through smem for coalesced stores ---
    __syncthreads();
    float* st = (float*)smem;                         // [128 n][132 m]
    const int c2 = (lane & 3) * 2;
    #pragma unroll
    for (int mt = 0; mt < 2; mt++)
        #pragma unroll
        for (int nt = 0; nt < 8; nt++) {
            const int m = wm0 + mt * 16 + r0;
            const int n = wn0 + nt * 8 + c2;
            st[n * 132 + m]           = acc[mt][nt][0];
            st[(n + 1) * 132 + m]     = acc[mt][nt][1];
            st[n * 132 + m + 8]       = acc[mt][nt][2];
            st[(n + 1) * 132 + m + 8] = acc[mt][nt][3];
        }
    __syncthreads();

    const int row = tid >> 1, half = tid & 1;         // n-row, m-half
    const float bv = __ldg(&bias[oc0 + row]);
    const float* srow = st + row * 132 + half * 64;
    float* dst = y + ((size_t)(b * kOC + oc0 + row)) * (kOH * kOW)
                   + oh0 * kOW + half * 64;
    #pragma unroll
    for (int t = 0; t < 16; t++) {
        float4 v = *(const float4*)(srow + t * 4);
        v.x += bv; v.y += bv; v.z += bv; v.w += bv;
        *(float4*)(dst + t * 4) = v;
    }
}

// ---------------------------------------------------------------------------
extern "C" void kernel_launch(void* const* d_in, const int* in_sizes, int n_in,
                              void* d_out, int out_size) {
    (void)in_sizes; (void)n_in; (void)out_size;
    const float* x    = (const float*)d_in[0];
    const float* w    = (const float*)d_in[1];
    const float* bias = (const float*)d_in[2];
    float* y = (float*)d_out;

    cudaFuncSetAttribute(conv_mma, cudaFuncAttributeMaxDynamicSharedMemorySize,
                         SMEM_TOT);

    fir_kernel<<<dim3(kUH, kB), 256>>>(x);
    wt_kernel<<<kOC, 256>>>(w);
    conv_mma<<<kB * (kOH / 4) * (kOC / 128), 256, SMEM_TOT>>>(bias, y);
}

// round 5
// speedup vs baseline: 3.6597x; 1.0089x over previous
#include <cuda_runtime.h>
#include <cstdint>

// ---------------------------------------------------------------------------
// Problem dims
// ---------------------------------------------------------------------------
constexpr int kB = 16, kC = 256, kH = 64, kW = 64;
constexpr int kUH = 65, kUW = 65;
constexpr int kOC = 256, kOH = 32, kOW = 32;

constexpr int KCH = 72;            // 9 rs taps * 8 ic-chunks of 32
constexpr int S   = 3;             // cp.async pipeline stages
constexpr int LDA = 36;            // padded smem stride in floats (conflict-free)
constexpr int TSZ = 128 * LDA * 4; // bytes per 128x32 operand tile (18432)
constexpr int SSZ = 2 * TSZ;       // stage = A tile + B tile
constexpr int SMEM_TOT = S * SSZ;  // 110592 B

// Scratch: u channels-last [b][h][w][c] (tf32-rounded), wt [rs][oc][ic]
__device__ __align__(1024) float g_u[(size_t)kB * kUH * kUW * kC];
__device__ __align__(1024) float g_wt[9 * kOC * kC];

// ---------------------------------------------------------------------------
// Helpers (sm_80-portable)
// ---------------------------------------------------------------------------
__device__ __forceinline__ uint32_t smem_u32(const void* p) {
    uint32_t a;
    asm("{ .reg .u64 t; cvta.to.shared.u64 t, %1; cvt.u32.u64 %0, t; }"
        : "=r"(a) : "l"(p));
    return a;
}
__device__ __forceinline__ float to_tf32(float v) {
    uint32_t r;
    asm("cvt.rna.tf32.f32 %0, %1;" : "=r"(r) : "f"(v));
    return __uint_as_float(r);
}
__device__ __forceinline__ void cp16(uint32_t dst, const void* src) {
    asm volatile("cp.async.cg.shared.global [%0], [%1], 16;"
                 :: "r"(dst), "l"(src) : "memory");
}
__device__ __forceinline__ void ldsm4(uint32_t addr, uint32_t& r0, uint32_t& r1,
                                      uint32_t& r2, uint32_t& r3) {
    asm volatile("ldmatrix.sync.aligned.m8n8.x4.shared.b16 {%0,%1,%2,%3}, [%4];"
                 : "=r"(r0), "=r"(r1), "=r"(r2), "=r"(r3) : "r"(addr));
}
__device__ __forceinline__ void mma_tf32(float* d, const uint32_t* a,
                                         uint32_t b0, uint32_t b1) {
    asm volatile(
        "mma.sync.aligned.m16n8k8.row.col.f32.tf32.tf32.f32 "
        "{%0,%1,%2,%3}, {%4,%5,%6,%7}, {%8,%9}, {%0,%1,%2,%3};"
        : "+f"(d[0]), "+f"(d[1]), "+f"(d[2]), "+f"(d[3])
        : "r"(a[0]), "r"(a[1]), "r"(a[2]), "r"(a[3]), "r"(b0), "r"(b1));
}

// ---------------------------------------------------------------------------
// Stage 1: separable 4x4 FIR, pad(2,2) -> u[b][h][w][c] channels-last (tf32 RN)
// Horizontal pass vectorized: 4 channels / thread -> one STG.128.
// ---------------------------------------------------------------------------
__global__ __launch_bounds__(256) void fir_kernel(const float* __restrict__ x) {
    __shared__ float vs[64 * 33];
    const int i = blockIdx.x, b = blockIdx.y;
    const int tid = threadIdx.x;
    const int wlane = tid & 63, cg = tid >> 6;
    const float fw[4] = {0.125f, 0.375f, 0.375f, 0.125f};

    for (int c0 = 0; c0 < kC; c0 += 32) {
        // vertical pass: vs[w][c] = sum_p f[p] x[b][c][i-2+p][w]
        #pragma unroll
        for (int k = 0; k < 8; k++) {
            const int c = cg * 8 + k;
            const float* xp = x + ((size_t)(b * kC + c0 + c) * kH) * kW + wlane;
            float acc = 0.f;
            #pragma unroll
            for (int p = 0; p < 4; p++) {
                const int xi = i - 2 + p;
                if (xi >= 0 && xi < kH) acc += fw[p] * xp[xi * kW];
            }
            vs[wlane * 33 + c] = acc;
        }
        __syncthreads();
        // horizontal pass: 4 consecutive channels per thread, float4 store
        for (int idx = tid; idx < kUW * 8; idx += 256) {
            const int wp = idx >> 3, c = (idx & 7) << 2;
            float a0 = 0.f, a1 = 0.f, a2 = 0.f, a3 = 0.f;
            #pragma unroll
            for (int q = 0; q < 4; q++) {
                const int wq = wp - 2 + q;
                if (wq >= 0 && wq < kW) {
                    const float* v = &vs[wq * 33 + c];
                    a0 += fw[q] * v[0];
                    a1 += fw[q] * v[1];
                    a2 += fw[q] * v[2];
                    a3 += fw[q] * v[3];
                }
            }
            float4 o = make_float4(to_tf32(a0), to_tf32(a1), to_tf32(a2), to_tf32(a3));
            *(float4*)(g_u + (((size_t)b * kUH + i) * kUW + wp) * kC + c0 + c) = o;
        }
        __syncthreads();
    }
}

// ---------------------------------------------------------------------------
// Weight transpose: w[oc][ic][rs] -> wt[rs][oc][ic] (tf32 RN)
// ---------------------------------------------------------------------------
__global__ __launch_bounds__(256) void wt_kernel(const float* __restrict__ w) {
    __shared__ float sm[kC * 9];
    const int oc = blockIdx.x;
    for (int idx = threadIdx.x; idx < kC * 9; idx += 256)
        sm[idx] = w[(size_t)oc * kC * 9 + idx];
    __syncthreads();
    for (int idx = threadIdx.x; idx < kC * 9; idx += 256) {
        const int rs = idx >> 8, ic = idx & 255;
        g_wt[((size_t)rs * kOC + oc) * kC + ic] = to_tf32(sm[ic * 9 + rs]);
    }
}

// ---------------------------------------------------------------------------
// Stage 2: implicit-GEMM conv via mma.sync tf32 (m16n8k8) + ldmatrix.x4.
// CTA: 128(M: 4 oh x 32 ow, one b) x 128(N: oc). 8 warps = 4(M) x 2(N),
// warp tile 32x64. K = 72 chunks of 32, 3-stage cp.async.
// ---------------------------------------------------------------------------
__global__ __launch_bounds__(256, 2)
void conv_mma(const float* __restrict__ bias, float* __restrict__ y) {
    extern __shared__ __align__(16) char smem[];
    const int tid = threadIdx.x, wid = tid >> 5, lane = tid & 31;
    const uint32_t sb = smem_u32(smem);

    const int mtile = blockIdx.x >> 1, ntile = blockIdx.x & 1;
    const int b = mtile >> 3, oh0 = (mtile & 7) << 2, oc0 = ntile << 7;
    const int wm0 = (wid & 3) * 32, wn0 = (wid >> 2) * 64;
    const float* ub = g_u + (size_t)b * kUH * kUW * kC;

    auto load_chunk = [&](int slot, int kc) {
        const int rs = kc >> 3, ic0 = (kc & 7) << 5;
        const int r = rs / 3, s = rs - r * 3;
        const uint32_t abase = sb + slot * SSZ;
        #pragma unroll
        for (int rep = 0; rep < 4; rep++) {
            const int unit = tid + rep * 256;        // 0..1023
            const int mi = unit >> 3, j = unit & 7;
            const int h = 2 * (oh0 + (mi >> 5)) + r;
            const int w = 2 * (mi & 31) + s;
            const float* src = ub + (((size_t)h * kUW + w) << 8) + ic0 + (j << 2);
            cp16(abase + mi * (LDA * 4) + j * 16, src);
        }
        const uint32_t bbase = abase + TSZ;
        const float* wsrc = g_wt + ((size_t)rs << 16) + ((size_t)oc0 << 8) + ic0;
        #pragma unroll
        for (int rep = 0; rep < 4; rep++) {
            const int unit = tid + rep * 256;        // 0..1023
            const int n = unit >> 3, j = unit & 7;
            cp16(bbase + n * (LDA * 4) + j * 16, wsrc + ((size_t)n << 8) + (j << 2));
        }
    };

    load_chunk(0, 0);
    asm volatile("cp.async.commit_group;" ::: "memory");
    load_chunk(1, 1);
    asm volatile("cp.async.commit_group;" ::: "memory");

    float acc[2][8][4];
    #pragma unroll
    for (int mt = 0; mt < 2; mt++)
        #pragma unroll
        for (int nt = 0; nt < 8; nt++)
            #pragma unroll
            for (int v = 0; v < 4; v++) acc[mt][nt][v] = 0.f;

    // ldmatrix lane address offset: lanes 0-15 -> rows 0-15 (k col 0),
    // lanes 16-31 -> rows 0-15 (k col 4)
    const uint32_t laneOff = ((lane & 15) * LDA + (lane >> 4) * 4) * 4;

    for (int i = 0; i < KCH; i++) {
        asm volatile("cp.async.wait_group 1;" ::: "memory");
        __syncthreads();

        if (i + 2 < KCH) load_chunk((i + 2) % S, i + 2);
        asm volatile("cp.async.commit_group;" ::: "memory");

        const uint32_t sbase = sb + (i % S) * SSZ;
        const uint32_t aBase = sbase + wm0 * (LDA * 4) + laneOff;
        const uint32_t bBase = sbase + TSZ + wn0 * (LDA * 4) + laneOff;

        #pragma unroll
        for (int kk = 0; kk < 4; kk++) {
            uint32_t a[2][4];
            ldsm4(aBase + kk * 32, a[0][0], a[0][1], a[0][2], a[0][3]);
            ldsm4(aBase + 16 * (LDA * 4) + kk * 32,
                  a[1][0], a[1][1], a[1][2], a[1][3]);
            #pragma unroll
            for (int ntp = 0; ntp < 4; ntp++) {
                uint32_t b0, b1, b2, b3;
                ldsm4(bBase + ntp * 16 * (LDA * 4) + kk * 32, b0, b1, b2, b3);
                mma_tf32(acc[0][2 * ntp],     a[0], b0, b2);
                mma_tf32(acc[0][2 * ntp + 1], a[0], b1, b3);
                mma_tf32(acc[1][2 * ntp],     a[1], b0, b2);
                mma_tf32(acc[1][2 * ntp + 1], a[1], b1, b3);
            }
        }
    }

    // --- epilogue: transpose through smem for coalesced stores ---
    __syncthreads();
    float* st = (float*)smem;                         // [128 n][132 m]
    const int r0 = lane >> 2;
    const int c2 = (lane & 3) * 2;
    #pragma unroll
    for (int mt = 0; mt < 2; mt++)
        #pragma unroll
        for (int nt = 0; nt < 8; nt++) {
            const int m = wm0 + mt * 16 + r0;
            const int n = wn0 + nt * 8 + c2;
            st[n * 132 + m]           = acc[mt][nt][0];
            st[(n + 1) * 132 + m]     = acc[mt][nt][1];
            st[n * 132 + m + 8]       = acc[mt][nt][2];
            st[(n + 1) * 132 + m + 8] = acc[mt][nt][3];
        }
    __syncthreads();

    const int row = tid >> 1, half = tid & 1;         // n-row, m-half
    const float bv = __ldg(&bias[oc0 + row]);
    const float* srow = st + row * 132 + half * 64;
    float* dst = y + ((size_t)(b * kOC + oc0 + row)) * (kOH * kOW)
                   + oh0 * kOW + half * 64;
    #pragma unroll
    for (int t = 0; t < 16; t++) {
        float4 v = *(const float4*)(srow + t * 4);
        v.x += bv; v.y += bv; v.z += bv; v.w += bv;
        *(float4*)(dst + t * 4) = v;
    }
}

// ---------------------------------------------------------------------------
extern "C" void kernel_launch(void* const* d_in, const int* in_sizes, int n_in,
                              void* d_out, int out_size) {
    (void)in_sizes; (void)n_in; (void)out_size;
    const float* x    = (const float*)d_in[0];
    const float* w    = (const float*)d_in[1];
    const float* bias = (const float*)d_in[2];
    float* y = (float*)d_out;

    cudaFuncSetAttribute(conv_mma, cudaFuncAttributeMaxDynamicSharedMemorySize,
                         SMEM_TOT);

    fir_kernel<<<dim3(kUH, kB), 256>>>(x);
    wt_kernel<<<kOC, 256>>>(w);
    conv_mma<<<kB * (kOH / 4) * (kOC / 128), 256, SMEM_TOT>>>(bias, y);
}

// round 6
// speedup vs baseline: 3.8433x; 1.0502x over previous
#include <cuda_runtime.h>
#include <cstdint>

// ---------------------------------------------------------------------------
// Problem dims
// ---------------------------------------------------------------------------
constexpr int kB = 16, kC = 256, kH = 64, kW = 64;
constexpr int kUH = 65, kUW = 65;
constexpr int kOC = 256, kOH = 32, kOW = 32;

constexpr int KCH = 72;                 // 9 rs taps * 8 ic-chunks of 32
constexpr int S   = 3;                  // pipeline stages
constexpr int CPAD = 36;                // padded channel stride (floats)
constexpr int AROW = kUW * CPAD * 4;    // 9360 B: one (icc,h) row of u2
constexpr int BTILE = 128 * CPAD * 4;   // 18432 B: one B tile (128 oc)
constexpr int B_IN_SLOT = 4 * AROW;     // 37440
constexpr int SSZ  = B_IN_SLOT + BTILE; // 55872
constexpr int MB_OFF = S * SSZ;         // 167616
constexpr int SMEM_TOT = MB_OFF + 64;   // mbarriers + pad

// Scratch (pre-padded, contiguous-tile layouts):
// g_u2[b][icc(8)][h(65)][w(65)][36]   (tf32-rounded, pad floats unread)
// g_wt2[rs(9)][icc(8)][oc(256)][36]
__device__ __align__(1024) float g_u2[(size_t)kB * 8 * kUH * kUW * CPAD];
__device__ __align__(1024) float g_wt2[9 * 8 * kOC * CPAD];

// ---------------------------------------------------------------------------
// Helpers
// ---------------------------------------------------------------------------
__device__ __forceinline__ uint32_t smem_u32(const void* p) {
    uint32_t a;
    asm("{ .reg .u64 t; cvta.to.shared.u64 t, %1; cvt.u32.u64 %0, t; }"
        : "=r"(a) : "l"(p));
    return a;
}
__device__ __forceinline__ float to_tf32(float v) {
    uint32_t r;
    asm("cvt.rna.tf32.f32 %0, %1;" : "=r"(r) : "f"(v));
    return __uint_as_float(r);
}
__device__ __forceinline__ void mbar_init(uint32_t a, uint32_t cnt) {
    asm volatile("mbarrier.init.shared.b64 [%0], %1;" :: "r"(a), "r"(cnt) : "memory");
}
__device__ __forceinline__ void mbar_expect(uint32_t a, uint32_t bytes) {
    asm volatile("mbarrier.arrive.expect_tx.shared.b64 _, [%0], %1;"
                 :: "r"(a), "r"(bytes) : "memory");
}
__device__ __forceinline__ void mwait(uint32_t mbar, uint32_t ph) {
    asm volatile(
        "{\n\t.reg .pred P;\n"
        "W%=:\n\tmbarrier.try_wait.parity.acquire.cta.shared::cta.b64 P, [%0], %1, 0x989680;\n\t"
        "@P bra D%=;\n\tbra W%=;\n"
        "D%=:\n\t}"
        :: "r"(mbar), "r"(ph) : "memory");
}
__device__ __forceinline__ void bulk_cp(uint32_t dst, const void* src,
                                        uint32_t bytes, uint32_t mbar) {
    asm volatile(
        "cp.async.bulk.shared::cta.global.mbarrier::complete_tx::bytes "
        "[%0], [%1], %2, [%3];"
        :: "r"(dst), "l"(src), "r"(bytes), "r"(mbar) : "memory");
}
__device__ __forceinline__ void ldsm4(uint32_t addr, uint32_t& r0, uint32_t& r1,
                                      uint32_t& r2, uint32_t& r3) {
    asm volatile("ldmatrix.sync.aligned.m8n8.x4.shared.b16 {%0,%1,%2,%3}, [%4];"
                 : "=r"(r0), "=r"(r1), "=r"(r2), "=r"(r3) : "r"(addr));
}
__device__ __forceinline__ void mma_tf32(float* d, const uint32_t* a,
                                         uint32_t b0, uint32_t b1) {
    asm volatile(
        "mma.sync.aligned.m16n8k8.row.col.f32.tf32.tf32.f32 "
        "{%0,%1,%2,%3}, {%4,%5,%6,%7}, {%8,%9}, {%0,%1,%2,%3};"
        : "+f"(d[0]), "+f"(d[1]), "+f"(d[2]), "+f"(d[3])
        : "r"(a[0]), "r"(a[1]), "r"(a[2]), "r"(a[3]), "r"(b0), "r"(b1));
}

// ---------------------------------------------------------------------------
// Stage 1: separable 4x4 FIR, pad(2,2) -> g_u2 chunk-major channels-last
// ---------------------------------------------------------------------------
__global__ __launch_bounds__(256) void fir_kernel(const float* __restrict__ x) {
    __shared__ float vs[64 * 33];
    const int i = blockIdx.x, b = blockIdx.y;
    const int tid = threadIdx.x;
    const int wlane = tid & 63, cg = tid >> 6;
    const float fw[4] = {0.125f, 0.375f, 0.375f, 0.125f};

    for (int c0 = 0; c0 < kC; c0 += 32) {
        #pragma unroll
        for (int k = 0; k < 8; k++) {
            const int c = cg * 8 + k;
            const float* xp = x + ((size_t)(b * kC + c0 + c) * kH) * kW + wlane;
            float acc = 0.f;
            #pragma unroll
            for (int p = 0; p < 4; p++) {
                const int xi = i - 2 + p;
                if (xi >= 0 && xi < kH) acc += fw[p] * xp[xi * kW];
            }
            vs[wlane * 33 + c] = acc;
        }
        __syncthreads();
        float* ubase = g_u2 + ((((size_t)b * 8 + (c0 >> 5)) * kUH + i) * kUW) * CPAD;
        for (int idx = tid; idx < kUW * 8; idx += 256) {
            const int wp = idx >> 3, c = (idx & 7) << 2;
            float a0 = 0.f, a1 = 0.f, a2 = 0.f, a3 = 0.f;
            #pragma unroll
            for (int q = 0; q < 4; q++) {
                const int wq = wp - 2 + q;
                if (wq >= 0 && wq < kW) {
                    const float* v = &vs[wq * 33 + c];
                    a0 += fw[q] * v[0];
                    a1 += fw[q] * v[1];
                    a2 += fw[q] * v[2];
                    a3 += fw[q] * v[3];
                }
            }
            float4 o = make_float4(to_tf32(a0), to_tf32(a1), to_tf32(a2), to_tf32(a3));
            *(float4*)(ubase + wp * CPAD + c) = o;
        }
        __syncthreads();
    }
}

// ---------------------------------------------------------------------------
// Weight transform: w[oc][ic][rs] -> g_wt2[rs][icc][oc][36] (tf32 RN)
// ---------------------------------------------------------------------------
__global__ __launch_bounds__(256) void wt_kernel(const float* __restrict__ w) {
    __shared__ float sm[kC * 9];
    const int oc = blockIdx.x;
    for (int idx = threadIdx.x; idx < kC * 9; idx += 256)
        sm[idx] = w[(size_t)oc * kC * 9 + idx];
    __syncthreads();
    for (int idx = threadIdx.x; idx < kC * 9; idx += 256) {
        const int rs = idx >> 8, ic = idx & 255;
        const int icc = ic >> 5, ic32 = ic & 31;
        g_wt2[(((size_t)rs * 8 + icc) * kOC + oc) * CPAD + ic32] =
            to_tf32(sm[ic * 9 + rs]);
    }
}

// ---------------------------------------------------------------------------
// Stage 2: implicit-GEMM conv, mma.sync tf32 + ldmatrix, bulk-copy pipeline.
// CTA: 128(M: 4 oh x 32 ow, one b) x 128(N: oc half). 8 warps = 4(M) x 2(N).
// Chunk kc = rs*8+icc: A = 4 contiguous u2 rows (h), B = one contiguous tile.
// ---------------------------------------------------------------------------
__global__ __launch_bounds__(256, 1)
void conv_mma(const float* __restrict__ bias, float* __restrict__ y) {
    extern __shared__ __align__(16) char smem[];
    const int tid = threadIdx.x, wid = tid >> 5, lane = tid & 31;
    const uint32_t sb = smem_u32(smem);
    const uint32_t mb = sb + MB_OFF;

    const int mtile = blockIdx.x >> 1, ntile = blockIdx.x & 1;
    const int b = mtile >> 3, oh0 = (mtile & 7) << 2, oc0 = ntile << 7;
    const int wohi = wid & 3, wn0 = (wid >> 2) * 64;

    if (tid == 0)
        for (int s = 0; s < S; s++) mbar_init(mb + 8 * s, 1);
    __syncthreads();

    auto issue = [&](int slot, int kc) {
        const int rs = kc >> 3, icc = kc & 7;
        const int r = rs / 3;
        const uint32_t mbar = mb + 8 * slot;
        const uint32_t dst = sb + slot * SSZ;
        mbar_expect(mbar, SSZ);
        const float* ub = g_u2 + (((size_t)b * 8 + icc) * kUH) * (kUW * CPAD);
        #pragma unroll
        for (int j = 0; j < 4; j++) {
            const int h = 2 * (oh0 + j) + r;
            bulk_cp(dst + j * AROW, ub + (size_t)h * (kUW * CPAD), AROW, mbar);
        }
        bulk_cp(dst + B_IN_SLOT,
                g_wt2 + (((size_t)rs * 8 + icc) * kOC + oc0) * CPAD, BTILE, mbar);
    };

    if (tid == 0) { issue(0, 0); issue(1, 1); }

    float acc[2][8][4];
    #pragma unroll
    for (int mt = 0; mt < 2; mt++)
        #pragma unroll
        for (int nt = 0; nt < 8; nt++)
            #pragma unroll
            for (int v = 0; v < 4; v++) acc[mt][nt][v] = 0.f;

    // ldmatrix lane offsets (byte units)
    const uint32_t laneA = (lane & 15) * (2 * CPAD * 4) + (lane >> 4) * 16;
    const uint32_t laneB = (lane & 15) * (CPAD * 4) + (lane >> 4) * 16;

    for (int i = 0; i < KCH; i++) {
        mwait(mb + 8 * (i % S), (uint32_t)((i / S) & 1));
        __syncthreads();                 // all warps done with chunk i-1's slot
        if (tid == 0 && i + 2 < KCH) issue((i + 2) % S, i + 2);

        const int rs = i >> 3;
        const int s = rs % 3;
        const uint32_t slotb = sb + (i % S) * SSZ;
        const uint32_t aBase = slotb + wohi * AROW + s * (CPAD * 4) + laneA;
        const uint32_t bBase = slotb + B_IN_SLOT + wn0 * (CPAD * 4) + laneB;

        #pragma unroll
        for (int kk = 0; kk < 4; kk++) {
            uint32_t a[2][4];
            ldsm4(aBase + kk * 32, a[0][0], a[0][1], a[0][2], a[0][3]);
            ldsm4(aBase + 16 * (2 * CPAD * 4) + kk * 32,
                  a[1][0], a[1][1], a[1][2], a[1][3]);
            #pragma unroll
            for (int ntp = 0; ntp < 4; ntp++) {
                uint32_t b0, b1, b2, b3;
                ldsm4(bBase + ntp * 16 * (CPAD * 4) + kk * 32, b0, b1, b2, b3);
                mma_tf32(acc[0][2 * ntp],     a[0], b0, b2);
                mma_tf32(acc[0][2 * ntp + 1], a[0], b1, b3);
                mma_tf32(acc[1][2 * ntp],     a[1], b0, b2);
                mma_tf32(acc[1][2 * ntp + 1], a[1], b1, b3);
            }
        }
    }

    // --- epilogue: transpose through smem for coalesced stores ---
    __syncthreads();
    float* st = (float*)smem;                         // [128 n][132 m]
    const int r0 = lane >> 2;
    const int c2 = (lane & 3) * 2;
    const int wm0 = wohi * 32;
    #pragma unroll
    for (int mt = 0; mt < 2; mt++)
        #pragma unroll
        for (int nt = 0; nt < 8; nt++) {
            const int m = wm0 + mt * 16 + r0;
            const int n = wn0 + nt * 8 + c2;
            st[n * 132 + m]           = acc[mt][nt][0];
            st[(n + 1) * 132 + m]     = acc[mt][nt][1];
            st[n * 132 + m + 8]       = acc[mt][nt][2];
            st[(n + 1) * 132 + m + 8] = acc[mt][nt][3];
        }
    __syncthreads();

    const int row = tid >> 1, half = tid & 1;         // n-row, m-half
    const float bv = __ldg(&bias[oc0 + row]);
    const float* srow = st + row * 132 + half * 64;
    float* dst = y + ((size_t)(b * kOC + oc0 + row)) * (kOH * kOW)
                   + oh0 * kOW + half * 64;
    #pragma unroll
    for (int t = 0; t < 16; t++) {
        float4 v = *(const float4*)(srow + t * 4);
        v.x += bv; v.y += bv; v.z += bv; v.w += bv;
        *(float4*)(dst + t * 4) = v;
    }
}

// ---------------------------------------------------------------------------
extern "C" void kernel_launch(void* const* d_in, const int* in_sizes, int n_in,
                              void* d_out, int out_size) {
    (void)in_sizes; (void)n_in; (void)out_size;
    const float* x    = (const float*)d_in[0];
    const float* w    = (const float*)d_in[1];
    const float* bias = (const float*)d_in[2];
    float* y = (float*)d_out;

    cudaFuncSetAttribute(conv_mma, cudaFuncAttributeMaxDynamicSharedMemorySize,
                         SMEM_TOT);

    fir_kernel<<<dim3(kUH, kB), 256>>>(x);
    wt_kernel<<<kOC, 256>>>(w);
    conv_mma<<<kB * (kOH / 4) * (kOC / 128), 256, SMEM_TOT>>>(bias, y);
}

// round 7
// speedup vs baseline: 4.1364x; 1.0763x over previous
#include <cuda_runtime.h>
#include <cstdint>

// ---------------------------------------------------------------------------
// Problem dims
// ---------------------------------------------------------------------------
constexpr int kB = 16, kC = 256, kH = 64, kW = 64;
constexpr int kUH = 65, kUW = 65;
constexpr int kOC = 256, kOH = 32, kOW = 32;

constexpr int KCH = 72;                 // 9 rs taps * 8 ic-chunks of 32
constexpr int S   = 3;                  // pipeline stages
constexpr int CPAD = 36;                // padded channel stride (floats)
constexpr int AROW = 64 * CPAD * 4;     // 9216 B: one trimmed (h) row in smem
constexpr int ASLOT = 4 * AROW;         // 36864
constexpr int BTILE = kOC * CPAD * 4;   // 36864 B: full 256-oc B tile
constexpr int SSZ  = ASLOT + BTILE;     // 73728
constexpr int MB_OFF = S * SSZ;         // 221184
constexpr int SMEM_TOT = MB_OFF + 64;   // + mbarriers

// Scratch (pre-padded, contiguous-tile layouts):
// g_u2[b][icc(8)][h(65)][w(65)][36]   (tf32-rounded, pad floats unread)
// g_wt2[rs(9)][icc(8)][oc(256)][36]
__device__ __align__(1024) float g_u2[(size_t)kB * 8 * kUH * kUW * CPAD];
__device__ __align__(1024) float g_wt2[9 * 8 * kOC * CPAD];

// ---------------------------------------------------------------------------
// Helpers
// ---------------------------------------------------------------------------
__device__ __forceinline__ uint32_t smem_u32(const void* p) {
    uint32_t a;
    asm("{ .reg .u64 t; cvta.to.shared.u64 t, %1; cvt.u32.u64 %0, t; }"
        : "=r"(a) : "l"(p));
    return a;
}
__device__ __forceinline__ float to_tf32(float v) {
    uint32_t r;
    asm("cvt.rna.tf32.f32 %0, %1;" : "=r"(r) : "f"(v));
    return __uint_as_float(r);
}
__device__ __forceinline__ void mbar_init(uint32_t a, uint32_t cnt) {
    asm volatile("mbarrier.init.shared.b64 [%0], %1;" :: "r"(a), "r"(cnt) : "memory");
}
__device__ __forceinline__ void mbar_expect(uint32_t a, uint32_t bytes) {
    asm volatile("mbarrier.arrive.expect_tx.shared.b64 _, [%0], %1;"
                 :: "r"(a), "r"(bytes) : "memory");
}
__device__ __forceinline__ void mwait(uint32_t mbar, uint32_t ph) {
    asm volatile(
        "{\n\t.reg .pred P;\n"
        "W%=:\n\tmbarrier.try_wait.parity.acquire.cta.shared::cta.b64 P, [%0], %1, 0x989680;\n\t"
        "@P bra D%=;\n\tbra W%=;\n"
        "D%=:\n\t}"
        :: "r"(mbar), "r"(ph) : "memory");
}
__device__ __forceinline__ void bulk_cp(uint32_t dst, const void* src,
                                        uint32_t bytes, uint32_t mbar) {
    asm volatile(
        "cp.async.bulk.shared::cta.global.mbarrier::complete_tx::bytes "
        "[%0], [%1], %2, [%3];"
        :: "r"(dst), "l"(src), "r"(bytes), "r"(mbar) : "memory");
}
__device__ __forceinline__ void ldsm4(uint32_t addr, uint32_t& r0, uint32_t& r1,
                                      uint32_t& r2, uint32_t& r3) {
    asm volatile("ldmatrix.sync.aligned.m8n8.x4.shared.b16 {%0,%1,%2,%3}, [%4];"
                 : "=r"(r0), "=r"(r1), "=r"(r2), "=r"(r3) : "r"(addr));
}
__device__ __forceinline__ void mma_tf32(float* d, const uint32_t* a,
                                         uint32_t b0, uint32_t b1) {
    asm volatile(
        "mma.sync.aligned.m16n8k8.row.col.f32.tf32.tf32.f32 "
        "{%0,%1,%2,%3}, {%4,%5,%6,%7}, {%8,%9}, {%0,%1,%2,%3};"
        : "+f"(d[0]), "+f"(d[1]), "+f"(d[2]), "+f"(d[3])
        : "r"(a[0]), "r"(a[1]), "r"(a[2]), "r"(a[3]), "r"(b0), "r"(b1));
}

// ---------------------------------------------------------------------------
// Stage 1: separable 4x4 FIR, pad(2,2) -> g_u2 chunk-major channels-last
// ---------------------------------------------------------------------------
__global__ __launch_bounds__(256) void fir_kernel(const float* __restrict__ x) {
    __shared__ float vs[64 * 33];
    const int i = blockIdx.x, b = blockIdx.y;
    const int tid = threadIdx.x;
    const int wlane = tid & 63, cg = tid >> 6;
    const float fw[4] = {0.125f, 0.375f, 0.375f, 0.125f};

    for (int c0 = 0; c0 < kC; c0 += 32) {
        #pragma unroll
        for (int k = 0; k < 8; k++) {
            const int c = cg * 8 + k;
            const float* xp = x + ((size_t)(b * kC + c0 + c) * kH) * kW + wlane;
            float acc = 0.f;
            #pragma unroll
            for (int p = 0; p < 4; p++) {
                const int xi = i - 2 + p;
                if (xi >= 0 && xi < kH) acc += fw[p] * xp[xi * kW];
            }
            vs[wlane * 33 + c] = acc;
        }
        __syncthreads();
        float* ubase = g_u2 + ((((size_t)b * 8 + (c0 >> 5)) * kUH + i) * kUW) * CPAD;
        for (int idx = tid; idx < kUW * 8; idx += 256) {
            const int wp = idx >> 3, c = (idx & 7) << 2;
            float a0 = 0.f, a1 = 0.f, a2 = 0.f, a3 = 0.f;
            #pragma unroll
            for (int q = 0; q < 4; q++) {
                const int wq = wp - 2 + q;
                if (wq >= 0 && wq < kW) {
                    const float* v = &vs[wq * 33 + c];
                    a0 += fw[q] * v[0];
                    a1 += fw[q] * v[1];
                    a2 += fw[q] * v[2];
                    a3 += fw[q] * v[3];
                }
            }
            float4 o = make_float4(to_tf32(a0), to_tf32(a1), to_tf32(a2), to_tf32(a3));
            *(float4*)(ubase + wp * CPAD + c) = o;
        }
        __syncthreads();
    }
}

// ---------------------------------------------------------------------------
// Weight transform: w[oc][ic][rs] -> g_wt2[rs][icc][oc][36] (tf32 RN)
// ---------------------------------------------------------------------------
__global__ __launch_bounds__(256) void wt_kernel(const float* __restrict__ w) {
    __shared__ float sm[kC * 9];
    const int oc = blockIdx.x;
    for (int idx = threadIdx.x; idx < kC * 9; idx += 256)
        sm[idx] = w[(size_t)oc * kC * 9 + idx];
    __syncthreads();
    for (int idx = threadIdx.x; idx < kC * 9; idx += 256) {
        const int rs = idx >> 8, ic = idx & 255;
        const int icc = ic >> 5, ic32 = ic & 31;
        g_wt2[(((size_t)rs * 8 + icc) * kOC + oc) * CPAD + ic32] =
            to_tf32(sm[ic * 9 + rs]);
    }
}

// ---------------------------------------------------------------------------
// Stage 2: implicit-GEMM conv, mma.sync tf32 + ldmatrix, bulk-copy pipeline.
// CTA: M=128 (4 oh x 32 ow, one b) x N=256 (ALL oc). 16 warps = 4(M) x 4(N),
// warp tile 32x64. 72 K-chunks of 32 ic; grid = 128 CTAs (single wave).
// ---------------------------------------------------------------------------
__global__ __launch_bounds__(512, 1)
void conv_mma(const float* __restrict__ bias, float* __restrict__ y) {
    extern __shared__ __align__(16) char smem[];
    const int tid = threadIdx.x, wid = tid >> 5, lane = tid & 31;
    const uint32_t sb = smem_u32(smem);
    const uint32_t mb = sb + MB_OFF;

    const int b = blockIdx.x >> 3, oh0 = (blockIdx.x & 7) << 2;
    const int wj = wid & 3;                 // m-subtile == oh row j
    const int wn0 = (wid >> 2) * 64;        // n-subtile

    if (tid == 0)
        for (int s = 0; s < S; s++) mbar_init(mb + 8 * s, 1);
    __syncthreads();

    auto issue = [&](int slot, int kc) {
        const int rs = kc >> 3, icc = kc & 7;
        const int r = rs / 3, s = rs % 3;
        const uint32_t mbar = mb + 8 * slot;
        const uint32_t dst = sb + slot * SSZ;
        mbar_expect(mbar, SSZ);
        const float* ub = g_u2 + (((size_t)b * 8 + icc) * kUH) * (kUW * CPAD);
        #pragma unroll
        for (int j = 0; j < 4; j++) {
            const int h = 2 * (oh0 + j) + r;
            bulk_cp(dst + j * AROW,
                    ub + (size_t)h * (kUW * CPAD) + s * CPAD, AROW, mbar);
        }
        bulk_cp(dst + ASLOT,
                g_wt2 + (((size_t)rs * 8 + icc) * kOC) * CPAD, BTILE, mbar);
    };

    if (tid == 0) { issue(0, 0); issue(1, 1); }

    float acc[2][8][4];
    #pragma unroll
    for (int mt = 0; mt < 2; mt++)
        #pragma unroll
        for (int nt = 0; nt < 8; nt++)
            #pragma unroll
            for (int v = 0; v < 4; v++) acc[mt][nt][v] = 0.f;

    // per-lane fragment offsets (bytes). A row (=ow) stride 288B, B row 144B.
    const uint32_t laneA = (lane & 15) * (2 * CPAD * 4) + (lane >> 4) * 16;
    const uint32_t laneB = (lane & 15) * (CPAD * 4) + (lane >> 4) * 16;

    for (int i = 0; i < KCH; i++) {
        mwait(mb + 8 * (i % S), (uint32_t)((i / S) & 1));
        __syncthreads();                 // all warps done with chunk i-1's slot
        if (tid == 0 && i + 2 < KCH) issue((i + 2) % S, i + 2);

        const uint32_t slotb = sb + (i % S) * SSZ;
        const uint32_t aBase = slotb + wj * AROW + laneA;
        const uint32_t bBase = slotb + ASLOT + wn0 * (CPAD * 4) + laneB;

        #pragma unroll
        for (int kk = 0; kk < 4; kk++) {
            uint32_t a[2][4];
            ldsm4(aBase + kk * 32, a[0][0], a[0][1], a[0][2], a[0][3]);
            ldsm4(aBase + 16 * (2 * CPAD * 4) + kk * 32,
                  a[1][0], a[1][1], a[1][2], a[1][3]);
            #pragma unroll
            for (int ntp = 0; ntp < 4; ntp++) {
                uint32_t b0, b1, b2, b3;
                ldsm4(bBase + ntp * 16 * (CPAD * 4) + kk * 32, b0, b1, b2, b3);
                mma_tf32(acc[0][2 * ntp],     a[0], b0, b2);
                mma_tf32(acc[0][2 * ntp + 1], a[0], b1, b3);
                mma_tf32(acc[1][2 * ntp],     a[1], b0, b2);
                mma_tf32(acc[1][2 * ntp + 1], a[1], b1, b3);
            }
        }
    }

    // --- epilogue: transpose through smem for coalesced stores ---
    __syncthreads();
    float* st = (float*)smem;                         // [256 n][132 m]
    const int r0 = lane >> 2;
    const int c2 = (lane & 3) * 2;
    const int wm0 = wj * 32;
    #pragma unroll
    for (int mt = 0; mt < 2; mt++)
        #pragma unroll
        for (int nt = 0; nt < 8; nt++) {
            const int m = wm0 + mt * 16 + r0;
            const int n = wn0 + nt * 8 + c2;
            st[n * 132 + m]           = acc[mt][nt][0];
            st[(n + 1) * 132 + m]     = acc[mt][nt][1];
            st[n * 132 + m + 8]       = acc[mt][nt][2];
            st[(n + 1) * 132 + m + 8] = acc[mt][nt][3];
        }
    __syncthreads();

    const int row = tid >> 1, half = tid & 1;         // n-row (oc), m-half
    const float bv = __ldg(&bias[row]);
    const float* srow = st + row * 132 + half * 64;
    float* dst = y + ((size_t)(b * kOC + row)) * (kOH * kOW)
                   + oh0 * kOW + half * 64;
    #pragma unroll
    for (int t = 0; t < 16; t++) {
        float4 v = *(const float4*)(srow + t * 4);
        v.x += bv; v.y += bv; v.z += bv; v.w += bv;
        *(float4*)(dst + t * 4) = v;
    }
}

// ---------------------------------------------------------------------------
extern "C" void kernel_launch(void* const* d_in, const int* in_sizes, int n_in,
                              void* d_out, int out_size) {
    (void)in_sizes; (void)n_in; (void)out_size;
    const float* x    = (const float*)d_in[0];
    const float* w    = (const float*)d_in[1];
    const float* bias = (const float*)d_in[2];
    float* y = (float*)d_out;

    cudaFuncSetAttribute(conv_mma, cudaFuncAttributeMaxDynamicSharedMemorySize,
                         SMEM_TOT);

    fir_kernel<<<dim3(kUH, kB), 256>>>(x);
    wt_kernel<<<kOC, 256>>>(w);
    conv_mma<<<kB * (kOH / 4), 512, SMEM_TOT>>>(bias, y);
}

// round 9
// speedup vs baseline: 5.9851x; 1.4469x over previous
#include <cuda_runtime.h>
#include <cuda_fp16.h>
#include <cstdint>

// ---------------------------------------------------------------------------
// Problem dims
// ---------------------------------------------------------------------------
constexpr int kB = 16, kC = 256, kH = 64, kW = 64;
constexpr int kUH = 65, kUW = 65;
constexpr int kOC = 256, kOH = 32, kOW = 32;

constexpr int KCH = 72;                 // 9 rs taps * 8 ic-chunks of 32
constexpr int S   = 4;                  // pipeline stages
constexpr int CPH = 40;                 // padded channel stride (halves) = 80B
constexpr int AROW = 64 * CPH * 2;      // 5120 B: one trimmed (h) row in smem
constexpr int ASLOT = 4 * AROW;         // 20480
constexpr int BTILE = kOC * CPH * 2;    // 20480 B
constexpr int SSZ  = ASLOT + BTILE;     // 40960
// epilogue transpose needs 256*132*4 = 135168 B; ring = 163840 B
constexpr int MB_OFF = S * SSZ;         // 163840
constexpr int SMEM_TOT = MB_OFF + 64;

// Scratch (fp16, pre-padded):
// g_u2[b][icc(8)][h(65)][w(65)][40]   g_wt2[rs(9)][icc(8)][oc(256)][40]
__device__ __align__(1024) __half g_u2[(size_t)kB * 8 * kUH * kUW * CPH];
__device__ __align__(1024) __half g_wt2[9 * 8 * kOC * CPH];

// ---------------------------------------------------------------------------
// Helpers
// ---------------------------------------------------------------------------
__device__ __forceinline__ uint32_t smem_u32(const void* p) {
    uint32_t a;
    asm("{ .reg .u64 t; cvta.to.shared.u64 t, %1; cvt.u32.u64 %0, t; }"
        : "=r"(a) : "l"(p));
    return a;
}
__device__ __forceinline__ uint32_t h2u(__half2 h) {
    return *reinterpret_cast<const uint32_t*>(&h);
}
__device__ __forceinline__ void mbar_init(uint32_t a, uint32_t cnt) {
    asm volatile("mbarrier.init.shared.b64 [%0], %1;" :: "r"(a), "r"(cnt) : "memory");
}
__device__ __forceinline__ void mbar_expect(uint32_t a, uint32_t bytes) {
    asm volatile("mbarrier.arrive.expect_tx.shared.b64 _, [%0], %1;"
                 :: "r"(a), "r"(bytes) : "memory");
}
__device__ __forceinline__ void mwait(uint32_t mbar, uint32_t ph) {
    asm volatile(
        "{\n\t.reg .pred P;\n"
        "W%=:\n\tmbarrier.try_wait.parity.acquire.cta.shared::cta.b64 P, [%0], %1, 0x989680;\n\t"
        "@P bra D%=;\n\tbra W%=;\n"
        "D%=:\n\t}"
        :: "r"(mbar), "r"(ph) : "memory");
}
__device__ __forceinline__ void bulk_cp(uint32_t dst, const void* src,
                                        uint32_t bytes, uint32_t mbar) {
    asm volatile(
        "cp.async.bulk.shared::cta.global.mbarrier::complete_tx::bytes "
        "[%0], [%1], %2, [%3];"
        :: "r"(dst), "l"(src), "r"(bytes), "r"(mbar) : "memory");
}
__device__ __forceinline__ void ldsm4(uint32_t addr, uint32_t& r0, uint32_t& r1,
                                      uint32_t& r2, uint32_t& r3) {
    asm volatile("ldmatrix.sync.aligned.m8n8.x4.shared.b16 {%0,%1,%2,%3}, [%4];"
                 : "=r"(r0), "=r"(r1), "=r"(r2), "=r"(r3) : "r"(addr));
}
__device__ __forceinline__ void mma_f16(float* d, const uint32_t* a,
                                        uint32_t b0, uint32_t b1) {
    asm volatile(
        "mma.sync.aligned.m16n8k16.row.col.f32.f16.f16.f32 "
        "{%0,%1,%2,%3}, {%4,%5,%6,%7}, {%8,%9}, {%0,%1,%2,%3};"
        : "+f"(d[0]), "+f"(d[1]), "+f"(d[2]), "+f"(d[3])
        : "r"(a[0]), "r"(a[1]), "r"(a[2]), "r"(a[3]), "r"(b0), "r"(b1));
}

// ---------------------------------------------------------------------------
// Stage 1: separable 4x4 FIR, pad(2,2) -> g_u2 chunk-major channels-last fp16
// ---------------------------------------------------------------------------
__global__ __launch_bounds__(256) void fir_kernel(const float* __restrict__ x) {
    __shared__ float vs[64 * 33];
    const int i = blockIdx.x, b = blockIdx.y;
    const int tid = threadIdx.x;
    const int wlane = tid & 63, cg = tid >> 6;
    const float fw[4] = {0.125f, 0.375f, 0.375f, 0.125f};

    for (int c0 = 0; c0 < kC; c0 += 32) {
        #pragma unroll
        for (int k = 0; k < 8; k++) {
            const int c = cg * 8 + k;
            const float* xp = x + ((size_t)(b * kC + c0 + c) * kH) * kW + wlane;
            float acc = 0.f;
            #pragma unroll
            for (int p = 0; p < 4; p++) {
                const int xi = i - 2 + p;
                if (xi >= 0 && xi < kH) acc += fw[p] * xp[xi * kW];
            }
            vs[wlane * 33 + c] = acc;
        }
        __syncthreads();
        __half* ubase = g_u2 +
            ((((size_t)b * 8 + (c0 >> 5)) * kUH + i) * kUW) * CPH;
        // 8 channels / thread -> one 16B store
        for (int idx = tid; idx < kUW * 4; idx += 256) {
            const int wp = idx >> 2, c = (idx & 3) << 3;
            float a[8];
            #pragma unroll
            for (int t = 0; t < 8; t++) a[t] = 0.f;
            #pragma unroll
            for (int q = 0; q < 4; q++) {
                const int wq = wp - 2 + q;
                if (wq >= 0 && wq < kW) {
                    const float* v = &vs[wq * 33 + c];
                    #pragma unroll
                    for (int t = 0; t < 8; t++) a[t] += fw[q] * v[t];
                }
            }
            uint4 o;
            o.x = h2u(__floats2half2_rn(a[0], a[1]));
            o.y = h2u(__floats2half2_rn(a[2], a[3]));
            o.z = h2u(__floats2half2_rn(a[4], a[5]));
            o.w = h2u(__floats2half2_rn(a[6], a[7]));
            *(uint4*)(ubase + wp * CPH + c) = o;
        }
        __syncthreads();
    }
}

// ---------------------------------------------------------------------------
// Weight transform: w[oc][ic][rs] -> g_wt2[rs][icc][oc][40] fp16
// ---------------------------------------------------------------------------
__global__ __launch_bounds__(256) void wt_kernel(const float* __restrict__ w) {
    __shared__ float sm[kC * 9];
    const int oc = blockIdx.x;
    for (int idx = threadIdx.x; idx < kC * 9; idx += 256)
        sm[idx] = w[(size_t)oc * kC * 9 + idx];
    __syncthreads();
    for (int idx = threadIdx.x; idx < kC * 9; idx += 256) {
        const int rs = idx >> 8, ic = idx & 255;
        const int icc = ic >> 5, ic32 = ic & 31;
        g_wt2[(((size_t)rs * 8 + icc) * kOC + oc) * CPH + ic32] =
            __float2half_rn(sm[ic * 9 + rs]);
    }
}

// ---------------------------------------------------------------------------
// Stage 2: implicit-GEMM conv, mma.sync fp16 (m16n8k16) + ldmatrix,
// bulk-copy 4-stage pipeline. CTA: M=128 (4 oh x 32 ow, one b) x N=256.
// 16 warps = 4(M) x 4(N), warp tile 32x64. 72 K-chunks of 32 ic. 128 CTAs.
// ---------------------------------------------------------------------------
__global__ __launch_bounds__(512, 1)
void conv_mma(const float* __restrict__ bias, float* __restrict__ y) {
    extern __shared__ __align__(16) char smem[];
    const int tid = threadIdx.x, wid = tid >> 5, lane = tid & 31;
    const uint32_t sb = smem_u32(smem);
    const uint32_t mb = sb + MB_OFF;

    const int b = blockIdx.x >> 3, oh0 = (blockIdx.x & 7) << 2;
    const int wj = wid & 3;                 // m-subtile == oh row j
    const int wn0 = (wid >> 2) * 64;        // n-subtile

    if (tid == 0)
        for (int s = 0; s < S; s++) mbar_init(mb + 8 * s, 1);
    __syncthreads();

    auto issue = [&](int slot, int kc) {
        const int rs = kc >> 3, icc = kc & 7;
        const int r = rs / 3, s = rs % 3;
        const uint32_t mbar = mb + 8 * slot;
        const uint32_t dst = sb + slot * SSZ;
        mbar_expect(mbar, SSZ);
        const __half* ub = g_u2 + (((size_t)b * 8 + icc) * kUH) * (kUW * CPH);
        #pragma unroll
        for (int j = 0; j < 4; j++) {
            const int h = 2 * (oh0 + j) + r;
            bulk_cp(dst + j * AROW,
                    ub + (size_t)h * (kUW * CPH) + s * CPH, AROW, mbar);
        }
        bulk_cp(dst + ASLOT,
                g_wt2 + (((size_t)rs * 8 + icc) * kOC) * CPH, BTILE, mbar);
    };

    if (tid == 0) { issue(0, 0); issue(1, 1); issue(2, 2); }

    float acc[2][8][4];
    #pragma unroll
    for (int mt = 0; mt < 2; mt++)
        #pragma unroll
        for (int nt = 0; nt < 8; nt++)
            #pragma unroll
            for (int v = 0; v < 4; v++) acc[mt][nt][v] = 0.f;

    // fragment lane offsets (bytes): A rows = ow (stride 2*80B), B rows = oc.
    const uint32_t laneA = (lane & 15) * (2 * CPH * 2) + (lane >> 4) * 16;
    const uint32_t laneB = (lane & 15) * (CPH * 2) + (lane >> 4) * 16;

    for (int i = 0; i < KCH; i++) {
        mwait(mb + 8 * (i % S), (uint32_t)((i / S) & 1));
        __syncthreads();                 // chunk i-1 fully consumed
        if (tid == 0 && i + S - 1 < KCH) issue((i + S - 1) % S, i + S - 1);

        const uint32_t slotb = sb + (i % S) * SSZ;
        const uint32_t aBase = slotb + wj * AROW + laneA;
        const uint32_t bBase = slotb + ASLOT + wn0 * (CPH * 2) + laneB;

        #pragma unroll
        for (int kk = 0; kk < 2; kk++) {          // 2 x k16
            uint32_t a[2][4];
            ldsm4(aBase + kk * 32, a[0][0], a[0][1], a[0][2], a[0][3]);
            ldsm4(aBase + 16 * (2 * CPH * 2) + kk * 32,
                  a[1][0], a[1][1], a[1][2], a[1][3]);
            #pragma unroll
            for (int ntp = 0; ntp < 4; ntp++) {
                uint32_t b0, b1, b2, b3;
                ldsm4(bBase + ntp * 16 * (CPH * 2) + kk * 32, b0, b1, b2, b3);
                mma_f16(acc[0][2 * ntp],     a[0], b0, b2);
                mma_f16(acc[0][2 * ntp + 1], a[0], b1, b3);
                mma_f16(acc[1][2 * ntp],     a[1], b0, b2);
                mma_f16(acc[1][2 * ntp + 1], a[1], b1, b3);
            }
        }
    }

    // --- epilogue: transpose through smem for coalesced stores ---
    __syncthreads();
    float* st = (float*)smem;                         // [256 n][132 m]
    const int r0 = lane >> 2;
    const int c2 = (lane & 3) * 2;
    const int wm0 = wj * 32;
    #pragma unroll
    for (int mt = 0; mt < 2; mt++)
        #pragma unroll
        for (int nt = 0; nt < 8; nt++) {
            const int m = wm0 + mt * 16 + r0;
            const int n = wn0 + nt * 8 + c2;
            st[n * 132 + m]           = acc[mt][nt][0];
            st[(n + 1) * 132 + m]     = acc[mt][nt][1];
            st[n * 132 + m + 8]       = acc[mt][nt][2];
            st[(n + 1) * 132 + m + 8] = acc[mt][nt][3];
        }
    __syncthreads();

    const int row = tid >> 1, half = tid & 1;         // n-row (oc), m-half
    const float bv = __ldg(&bias[row]);
    const float* srow = st + row * 132 + half * 64;
    float* dst = y + ((size_t)(b * kOC + row)) * (kOH * kOW)
                   + oh0 * kOW + half * 64;
    #pragma unroll
    for (int t = 0; t < 16; t++) {
        float4 v = *(const float4*)(srow + t * 4);
        v.x += bv; v.y += bv; v.z += bv; v.w += bv;
        *(float4*)(dst + t * 4) = v;
    }
}

// ---------------------------------------------------------------------------
extern "C" void kernel_launch(void* const* d_in, const int* in_sizes, int n_in,
                              void* d_out, int out_size) {
    (void)in_sizes; (void)n_in; (void)out_size;
    const float* x    = (const float*)d_in[0];
    const float* w    = (const float*)d_in[1];
    const float* bias = (const float*)d_in[2];
    float* y = (float*)d_out;

    cudaFuncSetAttribute(conv_mma, cudaFuncAttributeMaxDynamicSharedMemorySize,
                         SMEM_TOT);

    fir_kernel<<<dim3(kUH, kB), 256>>>(x);
    wt_kernel<<<kOC, 256>>>(w);
    conv_mma<<<kB * (kOH / 4), 512, SMEM_TOT>>>(bias, y);
}

// round 10
// speedup vs baseline: 6.2648x; 1.0467x over previous
#include <cuda_runtime.h>
#include <cuda_fp16.h>
#include <cstdint>

// ---------------------------------------------------------------------------
// Problem dims
// ---------------------------------------------------------------------------
constexpr int kB = 16, kC = 256, kH = 64, kW = 64;
constexpr int kUH = 65, kUW = 65;
constexpr int kOC = 256, kOH = 32, kOW = 32;

constexpr int KCH = 72;                 // 9 rs taps * 8 ic-chunks of 32
constexpr int S   = 4;                  // pipeline stages
constexpr int CPH = 40;                 // padded channel stride (halves) = 80B
constexpr int AROW = 64 * CPH * 2;      // 5120 B: one trimmed (h) row in smem
constexpr int ASLOT = 4 * AROW;         // 20480
constexpr int BTILE = kOC * CPH * 2;    // 20480 B
constexpr int SSZ  = ASLOT + BTILE;     // 40960
constexpr int MB_OFF = S * SSZ;         // 163840
constexpr int SMEM_TOT = MB_OFF + 64;

// Scratch (fp16, pre-padded):
// g_u2[b][icc(8)][h(65)][w(65)][40]   g_wt2[rs(9)][icc(8)][oc(256)][40]
__device__ __align__(1024) __half g_u2[(size_t)kB * 8 * kUH * kUW * CPH];
__device__ __align__(1024) __half g_wt2[9 * 8 * kOC * CPH];

// ---------------------------------------------------------------------------
// Helpers
// ---------------------------------------------------------------------------
__device__ __forceinline__ uint32_t smem_u32(const void* p) {
    uint32_t a;
    asm("{ .reg .u64 t; cvta.to.shared.u64 t, %1; cvt.u32.u64 %0, t; }"
        : "=r"(a) : "l"(p));
    return a;
}
__device__ __forceinline__ uint32_t h2u(__half2 h) {
    return *reinterpret_cast<const uint32_t*>(&h);
}
__device__ __forceinline__ void mbar_init(uint32_t a, uint32_t cnt) {
    asm volatile("mbarrier.init.shared.b64 [%0], %1;" :: "r"(a), "r"(cnt) : "memory");
}
__device__ __forceinline__ void mbar_expect(uint32_t a, uint32_t bytes) {
    asm volatile("mbarrier.arrive.expect_tx.shared.b64 _, [%0], %1;"
                 :: "r"(a), "r"(bytes) : "memory");
}
__device__ __forceinline__ void mwait(uint32_t mbar, uint32_t ph) {
    asm volatile(
        "{\n\t.reg .pred P;\n"
        "W%=:\n\tmbarrier.try_wait.parity.acquire.cta.shared::cta.b64 P, [%0], %1, 0x989680;\n\t"
        "@P bra D%=;\n\tbra W%=;\n"
        "D%=:\n\t}"
        :: "r"(mbar), "r"(ph) : "memory");
}
__device__ __forceinline__ void bulk_cp(uint32_t dst, const void* src,
                                        uint32_t bytes, uint32_t mbar) {
    asm volatile(
        "cp.async.bulk.shared::cta.global.mbarrier::complete_tx::bytes "
        "[%0], [%1], %2, [%3];"
        :: "r"(dst), "l"(src), "r"(bytes), "r"(mbar) : "memory");
}
__device__ __forceinline__ void ldsm4(uint32_t addr, uint32_t& r0, uint32_t& r1,
                                      uint32_t& r2, uint32_t& r3) {
    asm volatile("ldmatrix.sync.aligned.m8n8.x4.shared.b16 {%0,%1,%2,%3}, [%4];"
                 : "=r"(r0), "=r"(r1), "=r"(r2), "=r"(r3) : "r"(addr));
}
__device__ __forceinline__ void mma_f16(float* d, const uint32_t* a,
                                        uint32_t b0, uint32_t b1) {
    asm volatile(
        "mma.sync.aligned.m16n8k16.row.col.f32.f16.f16.f32 "
        "{%0,%1,%2,%3}, {%4,%5,%6,%7}, {%8,%9}, {%0,%1,%2,%3};"
        : "+f"(d[0]), "+f"(d[1]), "+f"(d[2]), "+f"(d[3])
        : "r"(a[0]), "r"(a[1]), "r"(a[2]), "r"(a[3]), "r"(b0), "r"(b1));
}

// ---------------------------------------------------------------------------
// Stage 1 (v3): separable 4x4 FIR, pad(2,2) -> g_u2, 4 output rows per block.
// Vertical: 7 shared x rows in registers serve 4 outputs (2.3x fewer loads).
// vs[t][w][36] pad 36: STS.128 / LDS.128 conflict-free per 8-lane phase.
// ---------------------------------------------------------------------------
constexpr int VP = 36;  // vs channel pad (floats)

__global__ __launch_bounds__(256) void fir_kernel(const float* __restrict__ x) {
    __shared__ float vs[4 * 64 * VP];       // 36864 B
    const int i0 = blockIdx.x * 4, b = blockIdx.y;
    const int tid = threadIdx.x;
    const float fw[4] = {0.125f, 0.375f, 0.375f, 0.125f};

    for (int c0 = 0; c0 < kC; c0 += 32) {
        // --- vertical pass: unit (cg of 4 ch, w). 512 units, 2 per thread ---
        #pragma unroll
        for (int uu = 0; uu < 2; uu++) {
            const int u = tid + uu * 256;
            const int w = u & 63, cg = u >> 6;          // cg 0..7
            float R[4][7];
            #pragma unroll
            for (int j = 0; j < 4; j++) {
                const float* xp =
                    x + ((size_t)(b * kC + c0 + cg * 4 + j) * kH) * kW + w;
                #pragma unroll
                for (int r = 0; r < 7; r++) {
                    const int xr = i0 - 2 + r;
                    R[j][r] = (xr >= 0 && xr < kH) ? xp[xr * kW] : 0.f;
                }
            }
            #pragma unroll
            for (int t = 0; t < 4; t++) {
                float4 v;
                v.x = fw[0]*R[0][t] + fw[1]*R[0][t+1] + fw[2]*R[0][t+2] + fw[3]*R[0][t+3];
                v.y = fw[0]*R[1][t] + fw[1]*R[1][t+1] + fw[2]*R[1][t+2] + fw[3]*R[1][t+3];
                v.z = fw[0]*R[2][t] + fw[1]*R[2][t+1] + fw[2]*R[2][t+2] + fw[3]*R[2][t+3];
                v.w = fw[0]*R[3][t] + fw[1]*R[3][t+1] + fw[2]*R[3][t+2] + fw[3]*R[3][t+3];
                *(float4*)&vs[(t * 64 + w) * VP + cg * 4] = v;
            }
        }
        __syncthreads();

        // --- horizontal pass: unit (t, wp, cg4). 4*65*8 = 2080 units ---
        const int icc = c0 >> 5;
        for (int idx = tid; idx < 4 * 65 * 8; idx += 256) {
            const int cg = idx & 7;
            const int rem = idx >> 3;            // 0..259
            const int wp = rem % 65, t = rem / 65;
            const int i = i0 + t;
            if (i >= kUH) continue;
            float4 acc = make_float4(0.f, 0.f, 0.f, 0.f);
            #pragma unroll
            for (int q = 0; q < 4; q++) {
                const int wq = wp - 2 + q;
                if (wq >= 0 && wq < kW) {
                    const float4 v =
                        *(const float4*)&vs[(t * 64 + wq) * VP + cg * 4];
                    acc.x += fw[q] * v.x;
                    acc.y += fw[q] * v.y;
                    acc.z += fw[q] * v.z;
                    acc.w += fw[q] * v.w;
                }
            }
            uint2 o;
            o.x = h2u(__floats2half2_rn(acc.x, acc.y));
            o.y = h2u(__floats2half2_rn(acc.z, acc.w));
            __half* dst = g_u2 +
                ((((size_t)b * 8 + icc) * kUH + i) * kUW + wp) * CPH + cg * 4;
            *(uint2*)dst = o;
        }
        __syncthreads();
    }
}

// ---------------------------------------------------------------------------
// Weight transform: w[oc][ic][rs] -> g_wt2[rs][icc][oc][40] fp16
// ---------------------------------------------------------------------------
__global__ __launch_bounds__(256) void wt_kernel(const float* __restrict__ w) {
    __shared__ float sm[kC * 9];
    const int oc = blockIdx.x;
    for (int idx = threadIdx.x; idx < kC * 9; idx += 256)
        sm[idx] = w[(size_t)oc * kC * 9 + idx];
    __syncthreads();
    for (int idx = threadIdx.x; idx < kC * 9; idx += 256) {
        const int rs = idx >> 8, ic = idx & 255;
        const int icc = ic >> 5, ic32 = ic & 31;
        g_wt2[(((size_t)rs * 8 + icc) * kOC + oc) * CPH + ic32] =
            __float2half_rn(sm[ic * 9 + rs]);
    }
}

// ---------------------------------------------------------------------------
// Stage 2: implicit-GEMM conv, mma.sync fp16 (m16n8k16) + ldmatrix,
// bulk-copy 4-stage pipeline. CTA: M=128 (4 oh x 32 ow, one b) x N=256.
// 16 warps = 4(M) x 4(N), warp tile 32x64. 72 K-chunks of 32 ic. 128 CTAs.
// ---------------------------------------------------------------------------
__global__ __launch_bounds__(512, 1)
void conv_mma(const float* __restrict__ bias, float* __restrict__ y) {
    extern __shared__ __align__(16) char smem[];
    const int tid = threadIdx.x, wid = tid >> 5, lane = tid & 31;
    const uint32_t sb = smem_u32(smem);
    const uint32_t mb = sb + MB_OFF;

    const int b = blockIdx.x >> 3, oh0 = (blockIdx.x & 7) << 2;
    const int wj = wid & 3;                 // m-subtile == oh row j
    const int wn0 = (wid >> 2) * 64;        // n-subtile

    if (tid == 0)
        for (int s = 0; s < S; s++) mbar_init(mb + 8 * s, 1);
    __syncthreads();

    auto issue = [&](int slot, int kc) {
        const int rs = kc >> 3, icc = kc & 7;
        const int r = rs / 3, s = rs % 3;
        const uint32_t mbar = mb + 8 * slot;
        const uint32_t dst = sb + slot * SSZ;
        mbar_expect(mbar, SSZ);
        const __half* ub = g_u2 + (((size_t)b * 8 + icc) * kUH) * (kUW * CPH);
        #pragma unroll
        for (int j = 0; j < 4; j++) {
            const int h = 2 * (oh0 + j) + r;
            bulk_cp(dst + j * AROW,
                    ub + (size_t)h * (kUW * CPH) + s * CPH, AROW, mbar);
        }
        bulk_cp(dst + ASLOT,
                g_wt2 + (((size_t)rs * 8 + icc) * kOC) * CPH, BTILE, mbar);
    };

    if (tid == 0) { issue(0, 0); issue(1, 1); issue(2, 2); }

    float acc[2][8][4];
    #pragma unroll
    for (int mt = 0; mt < 2; mt++)
        #pragma unroll
        for (int nt = 0; nt < 8; nt++)
            #pragma unroll
            for (int v = 0; v < 4; v++) acc[mt][nt][v] = 0.f;

    // fragment lane offsets (bytes): A rows = ow (stride 2*80B), B rows = oc.
    const uint32_t laneA = (lane & 15) * (2 * CPH * 2) + (lane >> 4) * 16;
    const uint32_t laneB = (lane & 15) * (CPH * 2) + (lane >> 4) * 16;

    for (int i = 0; i < KCH; i++) {
        mwait(mb + 8 * (i % S), (uint32_t)((i / S) & 1));
        __syncthreads();                 // chunk i-1 fully consumed
        if (tid == 0 && i + S - 1 < KCH) issue((i + S - 1) % S, i + S - 1);

        const uint32_t slotb = sb + (i % S) * SSZ;
        const uint32_t aBase = slotb + wj * AROW + laneA;
        const uint32_t bBase = slotb + ASLOT + wn0 * (CPH * 2) + laneB;

        #pragma unroll
        for (int kk = 0; kk < 2; kk++) {          // 2 x k16
            uint32_t a[2][4];
            ldsm4(aBase + kk * 32, a[0][0], a[0][1], a[0][2], a[0][3]);
            ldsm4(aBase + 16 * (2 * CPH * 2) + kk * 32,
                  a[1][0], a[1][1], a[1][2], a[1][3]);
            #pragma unroll
            for (int ntp = 0; ntp < 4; ntp++) {
                uint32_t b0, b1, b2, b3;
                ldsm4(bBase + ntp * 16 * (CPH * 2) + kk * 32, b0, b1, b2, b3);
                mma_f16(acc[0][2 * ntp],     a[0], b0, b2);
                mma_f16(acc[0][2 * ntp + 1], a[0], b1, b3);
                mma_f16(acc[1][2 * ntp],     a[1], b0, b2);
                mma_f16(acc[1][2 * ntp + 1], a[1], b1, b3);
            }
        }
    }

    // --- epilogue: transpose through smem for coalesced stores ---
    __syncthreads();
    float* st = (float*)smem;                         // [256 n][132 m]
    const int r0 = lane >> 2;
    const int c2 = (lane & 3) * 2;
    const int wm0 = wj * 32;
    #pragma unroll
    for (int mt = 0; mt < 2; mt++)
        #pragma unroll
        for (int nt = 0; nt < 8; nt++) {
            const int m = wm0 + mt * 16 + r0;
            const int n = wn0 + nt * 8 + c2;
            st[n * 132 + m]           = acc[mt][nt][0];
            st[(n + 1) * 132 + m]     = acc[mt][nt][1];
            st[n * 132 + m + 8]       = acc[mt][nt][2];
            st[(n + 1) * 132 + m + 8] = acc[mt][nt][3];
        }
    __syncthreads();

    const int row = tid >> 1, half = tid & 1;         // n-row (oc), m-half
    const float bv = __ldg(&bias[row]);
    const float* srow = st + row * 132 + half * 64;
    float* dst = y + ((size_t)(b * kOC + row)) * (kOH * kOW)
                   + oh0 * kOW + half * 64;
    #pragma unroll
    for (int t = 0; t < 16; t++) {
        float4 v = *(const float4*)(srow + t * 4);
        v.x += bv; v.y += bv; v.z += bv; v.w += bv;
        *(float4*)(dst + t * 4) = v;
    }
}

// ---------------------------------------------------------------------------
extern "C" void kernel_launch(void* const* d_in, const int* in_sizes, int n_in,
                              void* d_out, int out_size) {
    (void)in_sizes; (void)n_in; (void)out_size;
    const float* x    = (const float*)d_in[0];
    const float* w    = (const float*)d_in[1];
    const float* bias = (const float*)d_in[2];
    float* y = (float*)d_out;

    cudaFuncSetAttribute(conv_mma, cudaFuncAttributeMaxDynamicSharedMemorySize,
                         SMEM_TOT);

    fir_kernel<<<dim3(17, kB), 256>>>(x);
    wt_kernel<<<kOC, 256>>>(w);
    conv_mma<<<kB * (kOH / 4), 512, SMEM_TOT>>>(bias, y);
}

// round 11
// speedup vs baseline: 6.8479x; 1.0931x over previous
#include <cuda_runtime.h>
#include <cuda_fp16.h>
#include <cstdint>

// ---------------------------------------------------------------------------
// Problem dims
// ---------------------------------------------------------------------------
constexpr int kB = 16, kC = 256, kH = 64, kW = 64;
constexpr int kUH = 65, kUW = 65;
constexpr int kOC = 256, kOH = 32, kOW = 32;

constexpr int KCH = 72;                 // 9 rs taps * 8 ic-chunks of 32
constexpr int S   = 4;                  // pipeline stages
constexpr int CPH = 40;                 // padded channel stride (halves) = 80B
constexpr int AROW = 64 * CPH * 2;      // 5120 B: one trimmed (h) row in smem
constexpr int ASLOT = 4 * AROW;         // 20480
constexpr int BTILE = kOC * CPH * 2;    // 20480 B
constexpr int SSZ  = ASLOT + BTILE;     // 40960
constexpr int MB_OFF = S * SSZ;         // 163840: full[4] then consumed[4]
constexpr int SMEM_TOT = MB_OFF + 128;

// Scratch (fp16, pre-padded):
// g_u2[b][icc(8)][h(65)][w(65)][40]   g_wt2[rs(9)][icc(8)][oc(256)][40]
__device__ __align__(1024) __half g_u2[(size_t)kB * 8 * kUH * kUW * CPH];
__device__ __align__(1024) __half g_wt2[9 * 8 * kOC * CPH];

// ---------------------------------------------------------------------------
// Helpers
// ---------------------------------------------------------------------------
__device__ __forceinline__ uint32_t smem_u32(const void* p) {
    uint32_t a;
    asm("{ .reg .u64 t; cvta.to.shared.u64 t, %1; cvt.u32.u64 %0, t; }"
        : "=r"(a) : "l"(p));
    return a;
}
__device__ __forceinline__ uint32_t h2u(__half2 h) {
    return *reinterpret_cast<const uint32_t*>(&h);
}
__device__ __forceinline__ void mbar_init(uint32_t a, uint32_t cnt) {
    asm volatile("mbarrier.init.shared.b64 [%0], %1;" :: "r"(a), "r"(cnt) : "memory");
}
__device__ __forceinline__ void mbar_expect(uint32_t a, uint32_t bytes) {
    asm volatile("mbarrier.arrive.expect_tx.shared.b64 _, [%0], %1;"
                 :: "r"(a), "r"(bytes) : "memory");
}
__device__ __forceinline__ void mbar_arrive(uint32_t a) {
    asm volatile("mbarrier.arrive.release.cta.shared::cta.b64 _, [%0];"
                 :: "r"(a) : "memory");
}
__device__ __forceinline__ void mwait(uint32_t mbar, uint32_t ph) {
    asm volatile(
        "{\n\t.reg .pred P;\n"
        "W%=:\n\tmbarrier.try_wait.parity.acquire.cta.shared::cta.b64 P, [%0], %1, 0x989680;\n\t"
        "@P bra D%=;\n\tbra W%=;\n"
        "D%=:\n\t}"
        :: "r"(mbar), "r"(ph) : "memory");
}
__device__ __forceinline__ void bulk_cp(uint32_t dst, const void* src,
                                        uint32_t bytes, uint32_t mbar) {
    asm volatile(
        "cp.async.bulk.shared::cta.global.mbarrier::complete_tx::bytes "
        "[%0], [%1], %2, [%3];"
        :: "r"(dst), "l"(src), "r"(bytes), "r"(mbar) : "memory");
}
__device__ __forceinline__ void ldsm4(uint32_t addr, uint32_t& r0, uint32_t& r1,
                                      uint32_t& r2, uint32_t& r3) {
    asm volatile("ldmatrix.sync.aligned.m8n8.x4.shared.b16 {%0,%1,%2,%3}, [%4];"
                 : "=r"(r0), "=r"(r1), "=r"(r2), "=r"(r3) : "r"(addr));
}
__device__ __forceinline__ void mma_f16(float* d, const uint32_t* a,
                                        uint32_t b0, uint32_t b1) {
    asm volatile(
        "mma.sync.aligned.m16n8k16.row.col.f32.f16.f16.f32 "
        "{%0,%1,%2,%3}, {%4,%5,%6,%7}, {%8,%9}, {%0,%1,%2,%3};"
        : "+f"(d[0]), "+f"(d[1]), "+f"(d[2]), "+f"(d[3])
        : "r"(a[0]), "r"(a[1]), "r"(a[2]), "r"(a[3]), "r"(b0), "r"(b1));
}

// ---------------------------------------------------------------------------
// Stage 1 (v4): separable 4x4 FIR, 4 output rows / block, channels split
// over blockIdx.z (64 ch each) for occupancy. 1088 CTAs.
// ---------------------------------------------------------------------------
constexpr int VP = 36;  // vs channel pad (floats)

__global__ __launch_bounds__(256) void fir_kernel(const float* __restrict__ x) {
    __shared__ float vs[4 * 64 * VP];       // 36864 B
    const int i0 = blockIdx.x * 4, b = blockIdx.y;
    const int tid = threadIdx.x;
    const float fw[4] = {0.125f, 0.375f, 0.375f, 0.125f};

    for (int cc = 0; cc < 2; cc++) {
        const int c0 = blockIdx.z * 64 + cc * 32;
        // --- vertical pass: unit (cg of 4 ch, w). 512 units, 2 per thread ---
        #pragma unroll
        for (int uu = 0; uu < 2; uu++) {
            const int u = tid + uu * 256;
            const int w = u & 63, cg = u >> 6;          // cg 0..7
            float R[4][7];
            #pragma unroll
            for (int j = 0; j < 4; j++) {
                const float* xp =
                    x + ((size_t)(b * kC + c0 + cg * 4 + j) * kH) * kW + w;
                #pragma unroll
                for (int r = 0; r < 7; r++) {
                    const int xr = i0 - 2 + r;
                    R[j][r] = (xr >= 0 && xr < kH) ? xp[xr * kW] : 0.f;
                }
            }
            #pragma unroll
            for (int t = 0; t < 4; t++) {
                float4 v;
                v.x = fw[0]*R[0][t] + fw[1]*R[0][t+1] + fw[2]*R[0][t+2] + fw[3]*R[0][t+3];
                v.y = fw[0]*R[1][t] + fw[1]*R[1][t+1] + fw[2]*R[1][t+2] + fw[3]*R[1][t+3];
                v.z = fw[0]*R[2][t] + fw[1]*R[2][t+1] + fw[2]*R[2][t+2] + fw[3]*R[2][t+3];
                v.w = fw[0]*R[3][t] + fw[1]*R[3][t+1] + fw[2]*R[3][t+2] + fw[3]*R[3][t+3];
                *(float4*)&vs[(t * 64 + w) * VP + cg * 4] = v;
            }
        }
        __syncthreads();

        // --- horizontal pass: unit (t, wp, cg4). 4*65*8 = 2080 units ---
        const int icc = c0 >> 5;
        for (int idx = tid; idx < 4 * 65 * 8; idx += 256) {
            const int cg = idx & 7;
            const int rem = idx >> 3;            // 0..259
            const int wp = rem % 65, t = rem / 65;
            const int i = i0 + t;
            if (i >= kUH) continue;
            float4 acc = make_float4(0.f, 0.f, 0.f, 0.f);
            #pragma unroll
            for (int q = 0; q < 4; q++) {
                const int wq = wp - 2 + q;
                if (wq >= 0 && wq < kW) {
                    const float4 v =
                        *(const float4*)&vs[(t * 64 + wq) * VP + cg * 4];
                    acc.x += fw[q] * v.x;
                    acc.y += fw[q] * v.y;
                    acc.z += fw[q] * v.z;
                    acc.w += fw[q] * v.w;
                }
            }
            uint2 o;
            o.x = h2u(__floats2half2_rn(acc.x, acc.y));
            o.y = h2u(__floats2half2_rn(acc.z, acc.w));
            __half* dst = g_u2 +
                ((((size_t)b * 8 + icc) * kUH + i) * kUW + wp) * CPH + cg * 4;
            *(uint2*)dst = o;
        }
        __syncthreads();
    }
}

// ---------------------------------------------------------------------------
// Weight transform: w[oc][ic][rs] -> g_wt2[rs][icc][oc][40] fp16
// ---------------------------------------------------------------------------
__global__ __launch_bounds__(256) void wt_kernel(const float* __restrict__ w) {
    __shared__ float sm[kC * 9];
    const int oc = blockIdx.x;
    for (int idx = threadIdx.x; idx < kC * 9; idx += 256)
        sm[idx] = w[(size_t)oc * kC * 9 + idx];
    __syncthreads();
    for (int idx = threadIdx.x; idx < kC * 9; idx += 256) {
        const int rs = idx >> 8, ic = idx & 255;
        const int icc = ic >> 5, ic32 = ic & 31;
        g_wt2[(((size_t)rs * 8 + icc) * kOC + oc) * CPH + ic32] =
            __float2half_rn(sm[ic * 9 + rs]);
    }
}

// ---------------------------------------------------------------------------
// Stage 2: implicit-GEMM conv, mma.sync fp16 + ldmatrix, bulk-copy pipeline
// with distributed consumed-mbarriers (NO per-chunk __syncthreads).
// CTA: M=128 x N=256, 16 warps = 4(M) x 4(N). 72 K-chunks. 128 CTAs.
// ---------------------------------------------------------------------------
__global__ __launch_bounds__(512, 1)
void conv_mma(const float* __restrict__ bias, float* __restrict__ y) {
    extern __shared__ __align__(16) char smem[];
    const int tid = threadIdx.x, wid = tid >> 5, lane = tid & 31;
    const uint32_t sb = smem_u32(smem);
    const uint32_t mbF = sb + MB_OFF;           // full[s]
    const uint32_t mbC = sb + MB_OFF + 8 * S;   // consumed[s]

    const int b = blockIdx.x >> 3, oh0 = (blockIdx.x & 7) << 2;
    const int wj = wid & 3;                 // m-subtile == oh row j
    const int wn0 = (wid >> 2) * 64;        // n-subtile

    if (tid == 0)
        for (int s = 0; s < S; s++) {
            mbar_init(mbF + 8 * s, 1);
            mbar_init(mbC + 8 * s, 16);
        }
    __syncthreads();

    auto issue = [&](int slot, int kc) {
        const int rs = kc >> 3, icc = kc & 7;
        const int r = rs / 3, s = rs % 3;
        const uint32_t mbar = mbF + 8 * slot;
        const uint32_t dst = sb + slot * SSZ;
        mbar_expect(mbar, SSZ);
        const __half* ub = g_u2 + (((size_t)b * 8 + icc) * kUH) * (kUW * CPH);
        #pragma unroll
        for (int j = 0; j < 4; j++) {
            const int h = 2 * (oh0 + j) + r;
            bulk_cp(dst + j * AROW,
                    ub + (size_t)h * (kUW * CPH) + s * CPH, AROW, mbar);
        }
        bulk_cp(dst + ASLOT,
                g_wt2 + (((size_t)rs * 8 + icc) * kOC) * CPH, BTILE, mbar);
    };

    if (tid == 0) { issue(0, 0); issue(1, 1); issue(2, 2); }

    float acc[2][8][4];
    #pragma unroll
    for (int mt = 0; mt < 2; mt++)
        #pragma unroll
        for (int nt = 0; nt < 8; nt++)
            #pragma unroll
            for (int v = 0; v < 4; v++) acc[mt][nt][v] = 0.f;

    const uint32_t laneA = (lane & 15) * (2 * CPH * 2) + (lane >> 4) * 16;
    const uint32_t laneB = (lane & 15) * (CPH * 2) + (lane >> 4) * 16;

    for (int i = 0; i < KCH; i++) {
        // producer: issue chunk i+S-1 once slot's previous tenant is consumed
        if (wid == 0 && lane == 0) {
            const int j = i + S - 1;
            if (j < KCH) {
                if (i >= 1) mwait(mbC + 8 * ((i - 1) % S),
                                  (uint32_t)(((i - 1) / S) & 1));
                issue(j % S, j);
            }
        }
        __syncwarp();

        mwait(mbF + 8 * (i % S), (uint32_t)((i / S) & 1));

        const uint32_t slotb = sb + (i % S) * SSZ;
        const uint32_t aBase = slotb + wj * AROW + laneA;
        const uint32_t bBase = slotb + ASLOT + wn0 * (CPH * 2) + laneB;

        #pragma unroll
        for (int kk = 0; kk < 2; kk++) {          // 2 x k16
            uint32_t a[2][4];
            ldsm4(aBase + kk * 32, a[0][0], a[0][1], a[0][2], a[0][3]);
            ldsm4(aBase + 16 * (2 * CPH * 2) + kk * 32,
                  a[1][0], a[1][1], a[1][2], a[1][3]);
            #pragma unroll
            for (int ntp = 0; ntp < 4; ntp++) {
                uint32_t b0, b1, b2, b3;
                ldsm4(bBase + ntp * 16 * (CPH * 2) + kk * 32, b0, b1, b2, b3);
                mma_f16(acc[0][2 * ntp],     a[0], b0, b2);
                mma_f16(acc[0][2 * ntp + 1], a[0], b1, b3);
                mma_f16(acc[1][2 * ntp],     a[1], b0, b2);
                mma_f16(acc[1][2 * ntp + 1], a[1], b1, b3);
            }
        }
        __syncwarp();
        if (lane == 0) mbar_arrive(mbC + 8 * (i % S));   // this warp done
    }

    // --- epilogue: transpose through smem for coalesced stores ---
    __syncthreads();
    float* st = (float*)smem;                         // [256 n][132 m]
    const int r0 = lane >> 2;
    const int c2 = (lane & 3) * 2;
    const int wm0 = wj * 32;
    #pragma unroll
    for (int mt = 0; mt < 2; mt++)
        #pragma unroll
        for (int nt = 0; nt < 8; nt++) {
            const int m = wm0 + mt * 16 + r0;
            const int n = wn0 + nt * 8 + c2;
            st[n * 132 + m]           = acc[mt][nt][0];
            st[(n + 1) * 132 + m]     = acc[mt][nt][1];
            st[n * 132 + m + 8]       = acc[mt][nt][2];
            st[(n + 1) * 132 + m + 8] = acc[mt][nt][3];
        }
    __syncthreads();

    const int row = tid >> 1, half = tid & 1;         // n-row (oc), m-half
    const float bv = __ldg(&bias[row]);
    const float* srow = st + row * 132 + half * 64;
    float* dst = y + ((size_t)(b * kOC + row)) * (kOH * kOW)
                   + oh0 * kOW + half * 64;
    #pragma unroll
    for (int t = 0; t < 16; t++) {
        float4 v = *(const float4*)(srow + t * 4);
        v.x += bv; v.y += bv; v.z += bv; v.w += bv;
        *(float4*)(dst + t * 4) = v;
    }
}

// ---------------------------------------------------------------------------
extern "C" void kernel_launch(void* const* d_in, const int* in_sizes, int n_in,
                              void* d_out, int out_size) {
    (void)in_sizes; (void)n_in; (void)out_size;
    const float* x    = (const float*)d_in[0];
    const float* w    = (const float*)d_in[1];
    const float* bias = (const float*)d_in[2];
    float* y = (float*)d_out;

    cudaFuncSetAttribute(conv_mma, cudaFuncAttributeMaxDynamicSharedMemorySize,
                         SMEM_TOT);

    fir_kernel<<<dim3(17, kB, 4), 256>>>(x);
    wt_kernel<<<kOC, 256>>>(w);
    conv_mma<<<kB * (kOH / 4), 512, SMEM_TOT>>>(bias, y);
}

// round 12
// speedup vs baseline: 6.8576x; 1.0014x over previous
#include <cuda_runtime.h>
#include <cuda_fp16.h>
#include <cstdint>

// ---------------------------------------------------------------------------
// Problem dims
// ---------------------------------------------------------------------------
constexpr int kB = 16, kC = 256, kH = 64, kW = 64;
constexpr int kUH = 65, kUW = 65;
constexpr int kOC = 256, kOH = 32, kOW = 32;

constexpr int KCH = 72;                 // 9 rs taps * 8 ic-chunks of 32
constexpr int S   = 5;                  // pipeline stages
constexpr int CPH = 40;                 // padded channel stride (halves) = 80B
constexpr int AROW = 64 * CPH * 2;      // 5120 B: one trimmed (h) row in smem
constexpr int ASLOT = 4 * AROW;         // 20480
constexpr int BTILE = kOC * CPH * 2;    // 20480 B
constexpr int SSZ  = ASLOT + BTILE;     // 40960
constexpr int MB_OFF = S * SSZ;         // 204800: full[S] then consumed[S]
constexpr int SMEM_TOT = MB_OFF + 128;  // 204928

// Scratch (fp16, pre-padded):
// g_u2[b][icc(8)][h(65)][w(65)][40]   g_wt2[rs(9)][icc(8)][oc(256)][40]
__device__ __align__(1024) __half g_u2[(size_t)kB * 8 * kUH * kUW * CPH];
__device__ __align__(1024) __half g_wt2[9 * 8 * kOC * CPH];

// ---------------------------------------------------------------------------
// Helpers
// ---------------------------------------------------------------------------
__device__ __forceinline__ uint32_t smem_u32(const void* p) {
    uint32_t a;
    asm("{ .reg .u64 t; cvta.to.shared.u64 t, %1; cvt.u32.u64 %0, t; }"
        : "=r"(a) : "l"(p));
    return a;
}
__device__ __forceinline__ uint32_t h2u(__half2 h) {
    return *reinterpret_cast<const uint32_t*>(&h);
}
__device__ __forceinline__ void mbar_init(uint32_t a, uint32_t cnt) {
    asm volatile("mbarrier.init.shared.b64 [%0], %1;" :: "r"(a), "r"(cnt) : "memory");
}
__device__ __forceinline__ void mbar_expect(uint32_t a, uint32_t bytes) {
    asm volatile("mbarrier.arrive.expect_tx.shared.b64 _, [%0], %1;"
                 :: "r"(a), "r"(bytes) : "memory");
}
__device__ __forceinline__ void mbar_arrive(uint32_t a) {
    asm volatile("mbarrier.arrive.release.cta.shared::cta.b64 _, [%0];"
                 :: "r"(a) : "memory");
}
__device__ __forceinline__ void mwait(uint32_t mbar, uint32_t ph) {
    asm volatile(
        "{\n\t.reg .pred P;\n"
        "W%=:\n\tmbarrier.try_wait.parity.acquire.cta.shared::cta.b64 P, [%0], %1, 0x989680;\n\t"
        "@P bra D%=;\n\tbra W%=;\n"
        "D%=:\n\t}"
        :: "r"(mbar), "r"(ph) : "memory");
}
__device__ __forceinline__ void bulk_cp(uint32_t dst, const void* src,
                                        uint32_t bytes, uint32_t mbar) {
    asm volatile(
        "cp.async.bulk.shared::cta.global.mbarrier::complete_tx::bytes "
        "[%0], [%1], %2, [%3];"
        :: "r"(dst), "l"(src), "r"(bytes), "r"(mbar) : "memory");
}
__device__ __forceinline__ void ldsm4(uint32_t addr, uint32_t& r0, uint32_t& r1,
                                      uint32_t& r2, uint32_t& r3) {
    asm volatile("ldmatrix.sync.aligned.m8n8.x4.shared.b16 {%0,%1,%2,%3}, [%4];"
                 : "=r"(r0), "=r"(r1), "=r"(r2), "=r"(r3) : "r"(addr));
}
__device__ __forceinline__ void mma_f16(float* d, const uint32_t* a,
                                        uint32_t b0, uint32_t b1) {
    asm volatile(
        "mma.sync.aligned.m16n8k16.row.col.f32.f16.f16.f32 "
        "{%0,%1,%2,%3}, {%4,%5,%6,%7}, {%8,%9}, {%0,%1,%2,%3};"
        : "+f"(d[0]), "+f"(d[1]), "+f"(d[2]), "+f"(d[3])
        : "r"(a[0]), "r"(a[1]), "r"(a[2]), "r"(a[3]), "r"(b0), "r"(b1));
}

// ---------------------------------------------------------------------------
// Stage 1 (v5): separable 4x4 FIR, 4 output rows / block, one 32-channel
// chunk per block (blockIdx.z = icc). Power-of-2 loops, no div/mod.
// ---------------------------------------------------------------------------
constexpr int VP = 36;  // vs channel pad (floats)

__global__ __launch_bounds__(256) void fir_kernel(const float* __restrict__ x) {
    __shared__ float vs[4 * 64 * VP];       // 36864 B
    const int i0 = blockIdx.x * 4, b = blockIdx.y;
    const int icc = blockIdx.z;
    const int c0 = icc << 5;
    const int tid = threadIdx.x;
    const float fw[4] = {0.125f, 0.375f, 0.375f, 0.125f};

    // --- vertical pass: unit (cg of 4 ch, w). 512 units, 2 per thread ---
    #pragma unroll
    for (int uu = 0; uu < 2; uu++) {
        const int u = tid + uu * 256;
        const int w = u & 63, cg = u >> 6;          // cg 0..7
        float R[4][7];
        #pragma unroll
        for (int j = 0; j < 4; j++) {
            const float* xp =
                x + ((size_t)(b * kC + c0 + cg * 4 + j) * kH) * kW + w;
            #pragma unroll
            for (int r = 0; r < 7; r++) {
                const int xr = i0 - 2 + r;
                R[j][r] = (xr >= 0 && xr < kH) ? xp[xr * kW] : 0.f;
            }
        }
        #pragma unroll
        for (int t = 0; t < 4; t++) {
            float4 v;
            v.x = fw[0]*R[0][t] + fw[1]*R[0][t+1] + fw[2]*R[0][t+2] + fw[3]*R[0][t+3];
            v.y = fw[0]*R[1][t] + fw[1]*R[1][t+1] + fw[2]*R[1][t+2] + fw[3]*R[1][t+3];
            v.z = fw[0]*R[2][t] + fw[1]*R[2][t+1] + fw[2]*R[2][t+2] + fw[3]*R[2][t+3];
            v.w = fw[0]*R[3][t] + fw[1]*R[3][t+1] + fw[2]*R[3][t+2] + fw[3]*R[3][t+3];
            *(float4*)&vs[(t * 64 + w) * VP + cg * 4] = v;
        }
    }
    __syncthreads();

    const __half* ub0 = g_u2 + (((size_t)b * 8 + icc) * kUH) * (kUW * CPH);

    auto emit = [&](int t, int wp, int cg) {
        const int i = i0 + t;
        if (i >= kUH) return;
        float4 acc = make_float4(0.f, 0.f, 0.f, 0.f);
        #pragma unroll
        for (int q = 0; q < 4; q++) {
            const int wq = wp - 2 + q;
            if (wq >= 0 && wq < kW) {
                const float4 v = *(const float4*)&vs[(t * 64 + wq) * VP + cg * 4];
                acc.x += fw[q] * v.x;
                acc.y += fw[q] * v.y;
                acc.z += fw[q] * v.z;
                acc.w += fw[q] * v.w;
            }
        }
        uint2 o;
        o.x = h2u(__floats2half2_rn(acc.x, acc.y));
        o.y = h2u(__floats2half2_rn(acc.z, acc.w));
        *(uint2*)((__half*)ub0 + ((size_t)i * kUW + wp) * CPH + cg * 4) = o;
    };

    // --- horizontal pass main: 2048 units, 8 exact iterations, no div ---
    #pragma unroll
    for (int j = 0; j < 8; j++) {
        const int idx = tid + j * 256;
        emit(idx >> 9, (idx >> 3) & 63, idx & 7);
    }
    // edge column wp = 64: 32 units
    if (tid < 32) emit(tid >> 3, 64, tid & 7);
}

// ---------------------------------------------------------------------------
// Weight transform: w[oc][ic][rs] -> g_wt2[rs][icc][oc][40] fp16
// ---------------------------------------------------------------------------
__global__ __launch_bounds__(256) void wt_kernel(const float* __restrict__ w) {
    __shared__ float sm[kC * 9];
    const int oc = blockIdx.x;
    for (int idx = threadIdx.x; idx < kC * 9; idx += 256)
        sm[idx] = w[(size_t)oc * kC * 9 + idx];
    __syncthreads();
    for (int idx = threadIdx.x; idx < kC * 9; idx += 256) {
        const int rs = idx >> 8, ic = idx & 255;
        const int icc = ic >> 5, ic32 = ic & 31;
        g_wt2[(((size_t)rs * 8 + icc) * kOC + oc) * CPH + ic32] =
            __float2half_rn(sm[ic * 9 + rs]);
    }
}

// ---------------------------------------------------------------------------
// Stage 2: implicit-GEMM conv, mma.sync fp16 + ldmatrix, bulk-copy pipeline
// with distributed consumed-mbarriers (no per-chunk __syncthreads). S=5.
// CTA: M=128 x N=256, 16 warps = 4(M) x 4(N). 72 K-chunks. 128 CTAs.
// ---------------------------------------------------------------------------
__global__ __launch_bounds__(512, 1)
void conv_mma(const float* __restrict__ bias, float* __restrict__ y) {
    extern __shared__ __align__(16) char smem[];
    const int tid = threadIdx.x, wid = tid >> 5, lane = tid & 31;
    const uint32_t sb = smem_u32(smem);
    const uint32_t mbF = sb + MB_OFF;           // full[s]
    const uint32_t mbC = sb + MB_OFF + 8 * S;   // consumed[s]

    const int b = blockIdx.x >> 3, oh0 = (blockIdx.x & 7) << 2;
    const int wj = wid & 3;                 // m-subtile == oh row j
    const int wn0 = (wid >> 2) * 64;        // n-subtile

    if (tid == 0)
        for (int s = 0; s < S; s++) {
            mbar_init(mbF + 8 * s, 1);
            mbar_init(mbC + 8 * s, 16);
        }
    __syncthreads();

    auto issue = [&](int slot, int kc) {
        const int rs = kc >> 3, icc = kc & 7;
        const int r = rs / 3, s = rs % 3;
        const uint32_t mbar = mbF + 8 * slot;
        const uint32_t dst = sb + slot * SSZ;
        mbar_expect(mbar, SSZ);
        const __half* ub = g_u2 + (((size_t)b * 8 + icc) * kUH) * (kUW * CPH);
        #pragma unroll
        for (int j = 0; j < 4; j++) {
            const int h = 2 * (oh0 + j) + r;
            bulk_cp(dst + j * AROW,
                    ub + (size_t)h * (kUW * CPH) + s * CPH, AROW, mbar);
        }
        bulk_cp(dst + ASLOT,
                g_wt2 + (((size_t)rs * 8 + icc) * kOC) * CPH, BTILE, mbar);
    };

    if (tid == 0)
        for (int j = 0; j < S - 1; j++) issue(j, j);

    float acc[2][8][4];
    #pragma unroll
    for (int mt = 0; mt < 2; mt++)
        #pragma unroll
        for (int nt = 0; nt < 8; nt++)
            #pragma unroll
            for (int v = 0; v < 4; v++) acc[mt][nt][v] = 0.f;

    const uint32_t laneA = (lane & 15) * (2 * CPH * 2) + (lane >> 4) * 16;
    const uint32_t laneB = (lane & 15) * (CPH * 2) + (lane >> 4) * 16;

    for (int i = 0; i < KCH; i++) {
        // producer: issue chunk i+S-1 once slot's previous tenant is consumed
        if (wid == 0 && lane == 0) {
            const int j = i + S - 1;
            if (j < KCH) {
                if (i >= 1) mwait(mbC + 8 * ((i - 1) % S),
                                  (uint32_t)(((i - 1) / S) & 1));
                issue(j % S, j);
            }
        }
        __syncwarp();

        mwait(mbF + 8 * (i % S), (uint32_t)((i / S) & 1));

        const uint32_t slotb = sb + (i % S) * SSZ;
        const uint32_t aBase = slotb + wj * AROW + laneA;
        const uint32_t bBase = slotb + ASLOT + wn0 * (CPH * 2) + laneB;

        #pragma unroll
        for (int kk = 0; kk < 2; kk++) {          // 2 x k16
            uint32_t a[2][4];
            ldsm4(aBase + kk * 32, a[0][0], a[0][1], a[0][2], a[0][3]);
            ldsm4(aBase + 16 * (2 * CPH * 2) + kk * 32,
                  a[1][0], a[1][1], a[1][2], a[1][3]);
            #pragma unroll
            for (int ntp = 0; ntp < 4; ntp++) {
                uint32_t b0, b1, b2, b3;
                ldsm4(bBase + ntp * 16 * (CPH * 2) + kk * 32, b0, b1, b2, b3);
                mma_f16(acc[0][2 * ntp],     a[0], b0, b2);
                mma_f16(acc[0][2 * ntp + 1], a[0], b1, b3);
                mma_f16(acc[1][2 * ntp],     a[1], b0, b2);
                mma_f16(acc[1][2 * ntp + 1], a[1], b1, b3);
            }
        }
        __syncwarp();
        if (lane == 0) mbar_arrive(mbC + 8 * (i % S));   // this warp done
    }

    // --- epilogue: transpose through smem for coalesced stores ---
    __syncthreads();
    float* st = (float*)smem;                         // [256 n][132 m]
    const int r0 = lane >> 2;
    const int c2 = (lane & 3) * 2;
    const int wm0 = wj * 32;
    #pragma unroll
    for (int mt = 0; mt < 2; mt++)
        #pragma unroll
        for (int nt = 0; nt < 8; nt++) {
            const int m = wm0 + mt * 16 + r0;
            const int n = wn0 + nt * 8 + c2;
            st[n * 132 + m]           = acc[mt][nt][0];
            st[(n + 1) * 132 + m]     = acc[mt][nt][1];
            st[n * 132 + m + 8]       = acc[mt][nt][2];
            st[(n + 1) * 132 + m + 8] = acc[mt][nt][3];
        }
    __syncthreads();

    const int row = tid >> 1, half = tid & 1;         // n-row (oc), m-half
    const float bv = __ldg(&bias[row]);
    const float* srow = st + row * 132 + half * 64;
    float* dst = y + ((size_t)(b * kOC + row)) * (kOH * kOW)
                   + oh0 * kOW + half * 64;
    #pragma unroll
    for (int t = 0; t < 16; t++) {
        float4 v = *(const float4*)(srow + t * 4);
        v.x += bv; v.y += bv; v.z += bv; v.w += bv;
        *(float4*)(dst + t * 4) = v;
    }
}

// ---------------------------------------------------------------------------
extern "C" void kernel_launch(void* const* d_in, const int* in_sizes, int n_in,
                              void* d_out, int out_size) {
    (void)in_sizes; (void)n_in; (void)out_size;
    const float* x    = (const float*)d_in[0];
    const float* w    = (const float*)d_in[1];
    const float* bias = (const float*)d_in[2];
    float* y = (float*)d_out;

    cudaFuncSetAttribute(conv_mma, cudaFuncAttributeMaxDynamicSharedMemorySize,
                         SMEM_TOT);

    fir_kernel<<<dim3(17, kB, 8), 256>>>(x);
    wt_kernel<<<kOC, 256>>>(w);
    conv_mma<<<kB * (kOH / 4), 512, SMEM_TOT>>>(bias, y);
}

// round 14
// speedup vs baseline: 6.9746x; 1.0171x over previous
#include <cuda_runtime.h>
#include <cuda_fp16.h>
#include <cstdint>

// ---------------------------------------------------------------------------
// Problem dims
// ---------------------------------------------------------------------------
constexpr int kB = 16, kC = 256, kH = 64, kW = 64;
constexpr int kUH = 65, kUW = 65;
constexpr int kOC = 256, kOH = 32, kOW = 32;

constexpr int KCH = 72;                 // 9 rs taps * 8 ic-chunks of 32
constexpr int S   = 4;                  // pipeline stages (measured best)
constexpr int CPH = 40;                 // padded channel stride (halves) = 80B
constexpr int AROW = 64 * CPH * 2;      // 5120 B: one trimmed (h) row in smem
constexpr int ASLOT = 4 * AROW;         // 20480
constexpr int BTILE = kOC * CPH * 2;    // 20480 B
constexpr int SSZ  = ASLOT + BTILE;     // 40960
constexpr int MB_OFF = S * SSZ;         // 163840: full[S] then consumed[S]
constexpr int SMEM_TOT = MB_OFF + 128;

// Scratch (fp16, pre-padded):
// g_u2[b][icc(8)][h(65)][w(65)][40]   g_wt2[rs(9)][icc(8)][oc(256)][40]
__device__ __align__(1024) __half g_u2[(size_t)kB * 8 * kUH * kUW * CPH];
__device__ __align__(1024) __half g_wt2[9 * 8 * kOC * CPH];

// ---------------------------------------------------------------------------
// Helpers
// ---------------------------------------------------------------------------
__device__ __forceinline__ uint32_t smem_u32(const void* p) {
    uint32_t a;
    asm("{ .reg .u64 t; cvta.to.shared.u64 t, %1; cvt.u32.u64 %0, t; }"
        : "=r"(a) : "l"(p));
    return a;
}
__device__ __forceinline__ uint32_t h2u(__half2 h) {
    return *reinterpret_cast<const uint32_t*>(&h);
}
__device__ __forceinline__ void mbar_init(uint32_t a, uint32_t cnt) {
    asm volatile("mbarrier.init.shared.b64 [%0], %1;" :: "r"(a), "r"(cnt) : "memory");
}
__device__ __forceinline__ void mbar_expect(uint32_t a, uint32_t bytes) {
    asm volatile("mbarrier.arrive.expect_tx.shared.b64 _, [%0], %1;"
                 :: "r"(a), "r"(bytes) : "memory");
}
__device__ __forceinline__ void mbar_arrive(uint32_t a) {
    asm volatile("mbarrier.arrive.release.cta.shared::cta.b64 _, [%0];"
                 :: "r"(a) : "memory");
}
__device__ __forceinline__ void mwait(uint32_t mbar, uint32_t ph) {
    asm volatile(
        "{\n\t.reg .pred P;\n"
        "W%=:\n\tmbarrier.try_wait.parity.acquire.cta.shared::cta.b64 P, [%0], %1, 0x989680;\n\t"
        "@P bra D%=;\n\tbra W%=;\n"
        "D%=:\n\t}"
        :: "r"(mbar), "r"(ph) : "memory");
}
__device__ __forceinline__ void bulk_cp(uint32_t dst, const void* src,
                                        uint32_t bytes, uint32_t mbar) {
    asm volatile(
        "cp.async.bulk.shared::cta.global.mbarrier::complete_tx::bytes "
        "[%0], [%1], %2, [%3];"
        :: "r"(dst), "l"(src), "r"(bytes), "r"(mbar) : "memory");
}
__device__ __forceinline__ void ldsm4(uint32_t addr, uint32_t& r0, uint32_t& r1,
                                      uint32_t& r2, uint32_t& r3) {
    asm volatile("ldmatrix.sync.aligned.m8n8.x4.shared.b16 {%0,%1,%2,%3}, [%4];"
                 : "=r"(r0), "=r"(r1), "=r"(r2), "=r"(r3) : "r"(addr));
}
__device__ __forceinline__ void mma_f16(float* d, const uint32_t* a,
                                        uint32_t b0, uint32_t b1) {
    asm volatile(
        "mma.sync.aligned.m16n8k16.row.col.f32.f16.f16.f32 "
        "{%0,%1,%2,%3}, {%4,%5,%6,%7}, {%8,%9}, {%0,%1,%2,%3};"
        : "+f"(d[0]), "+f"(d[1]), "+f"(d[2]), "+f"(d[3])
        : "r"(a[0]), "r"(a[1]), "r"(a[2]), "r"(a[3]), "r"(b0), "r"(b1));
}

// ---------------------------------------------------------------------------
// Stage 1 (v5): separable 4x4 FIR, 4 output rows / block, one 32-channel
// chunk per block (blockIdx.z = icc). Power-of-2 loops, no div/mod.
// ---------------------------------------------------------------------------
constexpr int VP = 36;  // vs channel pad (floats)

__global__ __launch_bounds__(256) void fir_kernel(const float* __restrict__ x) {
    __shared__ float vs[4 * 64 * VP];       // 36864 B
    const int i0 = blockIdx.x * 4, b = blockIdx.y;
    const int icc = blockIdx.z;
    const int c0 = icc << 5;
    const int tid = threadIdx.x;
    const float fw[4] = {0.125f, 0.375f, 0.375f, 0.125f};

    // --- vertical pass: unit (cg of 4 ch, w). 512 units, 2 per thread ---
    #pragma unroll
    for (int uu = 0; uu < 2; uu++) {
        const int u = tid + uu * 256;
        const int w = u & 63, cg = u >> 6;          // cg 0..7
        float R[4][7];
        #pragma unroll
        for (int j = 0; j < 4; j++) {
            const float* xp =
                x + ((size_t)(b * kC + c0 + cg * 4 + j) * kH) * kW + w;
            #pragma unroll
            for (int r = 0; r < 7; r++) {
                const int xr = i0 - 2 + r;
                R[j][r] = (xr >= 0 && xr < kH) ? xp[xr * kW] : 0.f;
            }
        }
        #pragma unroll
        for (int t = 0; t < 4; t++) {
            float4 v;
            v.x = fw[0]*R[0][t] + fw[1]*R[0][t+1] + fw[2]*R[0][t+2] + fw[3]*R[0][t+3];
            v.y = fw[0]*R[1][t] + fw[1]*R[1][t+1] + fw[2]*R[1][t+2] + fw[3]*R[1][t+3];
            v.z = fw[0]*R[2][t] + fw[1]*R[2][t+1] + fw[2]*R[2][t+2] + fw[3]*R[2][t+3];
            v.w = fw[0]*R[3][t] + fw[1]*R[3][t+1] + fw[2]*R[3][t+2] + fw[3]*R[3][t+3];
            *(float4*)&vs[(t * 64 + w) * VP + cg * 4] = v;
        }
    }
    __syncthreads();

    const __half* ub0 = g_u2 + (((size_t)b * 8 + icc) * kUH) * (kUW * CPH);

    auto emit = [&](int t, int wp, int cg) {
        const int i = i0 + t;
        if (i >= kUH) return;
        float4 acc = make_float4(0.f, 0.f, 0.f, 0.f);
        #pragma unroll
        for (int q = 0; q < 4; q++) {
            const int wq = wp - 2 + q;
            if (wq >= 0 && wq < kW) {
                const float4 v = *(const float4*)&vs[(t * 64 + wq) * VP + cg * 4];
                acc.x += fw[q] * v.x;
                acc.y += fw[q] * v.y;
                acc.z += fw[q] * v.z;
                acc.w += fw[q] * v.w;
            }
        }
        uint2 o;
        o.x = h2u(__floats2half2_rn(acc.x, acc.y));
        o.y = h2u(__floats2half2_rn(acc.z, acc.w));
        *(uint2*)((__half*)ub0 + ((size_t)i * kUW + wp) * CPH + cg * 4) = o;
    };

    // --- horizontal pass main: 2048 units, 8 exact iterations, no div ---
    #pragma unroll
    for (int j = 0; j < 8; j++) {
        const int idx = tid + j * 256;
        emit(idx >> 9, (idx >> 3) & 63, idx & 7);
    }
    // edge column wp = 64: 32 units
    if (tid < 32) emit(tid >> 3, 64, tid & 7);
}

// ---------------------------------------------------------------------------
// Weight transform: w[oc][ic][rs] -> g_wt2[rs][icc][oc][40] fp16
// ---------------------------------------------------------------------------
__global__ __launch_bounds__(256) void wt_kernel(const float* __restrict__ w) {
    __shared__ float sm[kC * 9];
    const int oc = blockIdx.x;
    for (int idx = threadIdx.x; idx < kC * 9; idx += 256)
        sm[idx] = w[(size_t)oc * kC * 9 + idx];
    __syncthreads();
    for (int idx = threadIdx.x; idx < kC * 9; idx += 256) {
        const int rs = idx >> 8, ic = idx & 255;
        const int icc = ic >> 5, ic32 = ic & 31;
        g_wt2[(((size_t)rs * 8 + icc) * kOC + oc) * CPH + ic32] =
            __float2half_rn(sm[ic * 9 + rs]);
    }
}

// ---------------------------------------------------------------------------
// Stage 2: implicit-GEMM conv, mma.sync fp16 + ldmatrix, bulk-copy pipeline
// with distributed consumed-mbarriers (no per-chunk __syncthreads). S=4.
// CTA: M=128 x N=256, 16 warps = 4(M) x 4(N). 72 K-chunks. 128 CTAs.
// ---------------------------------------------------------------------------
__global__ __launch_bounds__(512, 1)
void conv_mma(const float* __restrict__ bias, float* __restrict__ y) {
    extern __shared__ __align__(16) char smem[];
    const int tid = threadIdx.x, wid = tid >> 5, lane = tid & 31;
    const uint32_t sb = smem_u32(smem);
    const uint32_t mbF = sb + MB_OFF;           // full[s]
    const uint32_t mbC = sb + MB_OFF + 8 * S;   // consumed[s]

    const int b = blockIdx.x >> 3, oh0 = (blockIdx.x & 7) << 2;
    const int wj = wid & 3;                 // m-subtile == oh row j
    const int wn0 = (wid >> 2) * 64;        // n-subtile

    if (tid == 0)
        for (int s = 0; s < S; s++) {
            mbar_init(mbF + 8 * s, 1);
            mbar_init(mbC + 8 * s, 16);
        }
    __syncthreads();

    auto issue = [&](int slot, int kc) {
        const int rs = kc >> 3, icc = kc & 7;
        const int r = rs / 3, s = rs % 3;
        const uint32_t mbar = mbF + 8 * slot;
        const uint32_t dst = sb + slot * SSZ;
        mbar_expect(mbar, SSZ);
        const __half* ub = g_u2 + (((size_t)b * 8 + icc) * kUH) * (kUW * CPH);
        #pragma unroll
        for (int j = 0; j < 4; j++) {
            const int h = 2 * (oh0 + j) + r;
            bulk_cp(dst + j * AROW,
                    ub + (size_t)h * (kUW * CPH) + s * CPH, AROW, mbar);
        }
        bulk_cp(dst + ASLOT,
                g_wt2 + (((size_t)rs * 8 + icc) * kOC) * CPH, BTILE, mbar);
    };

    if (tid == 0)
        for (int j = 0; j < S - 1; j++) issue(j, j);

    float acc[2][8][4];
    #pragma unroll
    for (int mt = 0; mt < 2; mt++)
        #pragma unroll
        for (int nt = 0; nt < 8; nt++)
            #pragma unroll
            for (int v = 0; v < 4; v++) acc[mt][nt][v] = 0.f;

    const uint32_t laneA = (lane & 15) * (2 * CPH * 2) + (lane >> 4) * 16;
    const uint32_t laneB = (lane & 15) * (CPH * 2) + (lane >> 4) * 16;

    for (int i = 0; i < KCH; i++) {
        // producer: issue chunk i+S-1 once slot's previous tenant is consumed
        if (wid == 0 && lane == 0) {
            const int j = i + S - 1;
            if (j < KCH) {
                if (i >= 1) mwait(mbC + 8 * ((i - 1) % S),
                                  (uint32_t)(((i - 1) / S) & 1));
                issue(j % S, j);
            }
        }
        // (no __syncwarp: divergence reconverges at the mwait below)

        mwait(mbF + 8 * (i % S), (uint32_t)((i / S) & 1));

        const uint32_t slotb = sb + (i % S) * SSZ;
        const uint32_t aBase = slotb + wj * AROW + laneA;
        const uint32_t bBase = slotb + ASLOT + wn0 * (CPH * 2) + laneB;

        #pragma unroll
        for (int kk = 0; kk < 2; kk++) {          // 2 x k16
            uint32_t a[2][4];
            ldsm4(aBase + kk * 32, a[0][0], a[0][1], a[0][2], a[0][3]);
            ldsm4(aBase + 16 * (2 * CPH * 2) + kk * 32,
                  a[1][0], a[1][1], a[1][2], a[1][3]);
            #pragma unroll
            for (int ntp = 0; ntp < 4; ntp++) {
                uint32_t b0, b1, b2, b3;
                ldsm4(bBase + ntp * 16 * (CPH * 2) + kk * 32, b0, b1, b2, b3);
                mma_f16(acc[0][2 * ntp],     a[0], b0, b2);
                mma_f16(acc[0][2 * ntp + 1], a[0], b1, b3);
                mma_f16(acc[1][2 * ntp],     a[1], b0, b2);
                mma_f16(acc[1][2 * ntp + 1], a[1], b1, b3);
            }
        }
        __syncwarp();                               // all lanes done reading slot
        if (lane == 0) mbar_arrive(mbC + 8 * (i % S));
    }

    // --- epilogue: transpose through smem for coalesced stores ---
    __syncthreads();
    float* st = (float*)smem;                         // [256 n][132 m]
    const int r0 = lane >> 2;
    const int c2 = (lane & 3) * 2;
    const int wm0 = wj * 32;
    #pragma unroll
    for (int mt = 0; mt < 2; mt++)
        #pragma unroll
        for (int nt = 0; nt < 8; nt++) {
            const int m = wm0 + mt * 16 + r0;
            const int n = wn0 + nt * 8 + c2;
            st[n * 132 + m]           = acc[mt][nt][0];
            st[(n + 1) * 132 + m]     = acc[mt][nt][1];
            st[n * 132 + m + 8]       = acc[mt][nt][2];
            st[(n + 1) * 132 + m + 8] = acc[mt][nt][3];
        }
    __syncthreads();

    const int row = tid >> 1, half = tid & 1;         // n-row (oc), m-half
    const float bv = __ldg(&bias[row]);
    const float* srow = st + row * 132 + half * 64;
    float* dst = y + ((size_t)(b * kOC + row)) * (kOH * kOW)
                   + oh0 * kOW + half * 64;
    #pragma unroll
    for (int t = 0; t < 16; t++) {
        float4 v = *(const float4*)(srow + t * 4);
        v.x += bv; v.y += bv; v.z += bv; v.w += bv;
        *(float4*)(dst + t * 4) = v;
    }
}

// ---------------------------------------------------------------------------
extern "C" void kernel_launch(void* const* d_in, const int* in_sizes, int n_in,
                              void* d_out, int out_size) {
    (void)in_sizes; (void)n_in; (void)out_size;
    const float* x    = (const float*)d_in[0];
    const float* w    = (const float*)d_in[1];
    const float* bias = (const float*)d_in[2];
    float* y = (float*)d_out;

    cudaFuncSetAttribute(conv_mma, cudaFuncAttributeMaxDynamicSharedMemorySize,
                         SMEM_TOT);

    fir_kernel<<<dim3(17, kB, 8), 256>>>(x);
    wt_kernel<<<kOC, 256>>>(w);
    conv_mma<<<kB * (kOH / 4), 512, SMEM_TOT>>>(bias, y);
}

// round 15
// speedup vs baseline: 6.9847x; 1.0014x over previous
#include <cuda_runtime.h>
#include <cuda_fp16.h>
#include <cstdint>

// ---------------------------------------------------------------------------
// Problem dims
// ---------------------------------------------------------------------------
constexpr int kB = 16, kC = 256, kH = 64, kW = 64;
constexpr int kUH = 65, kUW = 65;
constexpr int kOC = 256, kOH = 32, kOW = 32;

constexpr int KCH = 72;                 // 9 rs taps * 8 ic-chunks of 32
constexpr int S   = 4;                  // pipeline stages (measured best)
constexpr int CPH = 40;                 // padded channel stride (halves) = 80B
constexpr int AROW = 64 * CPH * 2;      // 5120 B: one trimmed (h) row in smem
constexpr int ASLOT = 4 * AROW;         // 20480
constexpr int BTILE = kOC * CPH * 2;    // 20480 B
constexpr int SSZ  = ASLOT + BTILE;     // 40960
constexpr int MB_OFF = S * SSZ;         // 163840: full[S] then consumed[S]
constexpr int SMEM_TOT = MB_OFF + 128;

// Scratch (fp16, pre-padded):
// g_u2[b][icc(8)][h(65)][w(65)][40]   g_wt2[rs(9)][icc(8)][oc(256)][40]
__device__ __align__(1024) __half g_u2[(size_t)kB * 8 * kUH * kUW * CPH];
__device__ __align__(1024) __half g_wt2[9 * 8 * kOC * CPH];

// ---------------------------------------------------------------------------
// Helpers
// ---------------------------------------------------------------------------
__device__ __forceinline__ uint32_t smem_u32(const void* p) {
    uint32_t a;
    asm("{ .reg .u64 t; cvta.to.shared.u64 t, %1; cvt.u32.u64 %0, t; }"
        : "=r"(a) : "l"(p));
    return a;
}
__device__ __forceinline__ uint32_t h2u(__half2 h) {
    return *reinterpret_cast<const uint32_t*>(&h);
}
__device__ __forceinline__ void mbar_init(uint32_t a, uint32_t cnt) {
    asm volatile("mbarrier.init.shared.b64 [%0], %1;" :: "r"(a), "r"(cnt) : "memory");
}
__device__ __forceinline__ void mbar_expect(uint32_t a, uint32_t bytes) {
    asm volatile("mbarrier.arrive.expect_tx.shared.b64 _, [%0], %1;"
                 :: "r"(a), "r"(bytes) : "memory");
}
__device__ __forceinline__ void mbar_arrive(uint32_t a) {
    asm volatile("mbarrier.arrive.release.cta.shared::cta.b64 _, [%0];"
                 :: "r"(a) : "memory");
}
__device__ __forceinline__ void mwait(uint32_t mbar, uint32_t ph) {
    asm volatile(
        "{\n\t.reg .pred P;\n"
        "W%=:\n\tmbarrier.try_wait.parity.acquire.cta.shared::cta.b64 P, [%0], %1, 0x989680;\n\t"
        "@P bra D%=;\n\tbra W%=;\n"
        "D%=:\n\t}"
        :: "r"(mbar), "r"(ph) : "memory");
}
__device__ __forceinline__ void bulk_cp(uint32_t dst, const void* src,
                                        uint32_t bytes, uint32_t mbar) {
    asm volatile(
        "cp.async.bulk.shared::cta.global.mbarrier::complete_tx::bytes "
        "[%0], [%1], %2, [%3];"
        :: "r"(dst), "l"(src), "r"(bytes), "r"(mbar) : "memory");
}
__device__ __forceinline__ void ldsm4(uint32_t addr, uint32_t& r0, uint32_t& r1,
                                      uint32_t& r2, uint32_t& r3) {
    asm volatile("ldmatrix.sync.aligned.m8n8.x4.shared.b16 {%0,%1,%2,%3}, [%4];"
                 : "=r"(r0), "=r"(r1), "=r"(r2), "=r"(r3) : "r"(addr));
}
__device__ __forceinline__ void mma_f16(float* d, const uint32_t* a,
                                        uint32_t b0, uint32_t b1) {
    asm volatile(
        "mma.sync.aligned.m16n8k16.row.col.f32.f16.f16.f32 "
        "{%0,%1,%2,%3}, {%4,%5,%6,%7}, {%8,%9}, {%0,%1,%2,%3};"
        : "+f"(d[0]), "+f"(d[1]), "+f"(d[2]), "+f"(d[3])
        : "r"(a[0]), "r"(a[1]), "r"(a[2]), "r"(a[3]), "r"(b0), "r"(b1));
}

// ---------------------------------------------------------------------------
// Stage 1 (v5): separable 4x4 FIR, 4 output rows / block, one 32-channel
// chunk per block (blockIdx.z = icc). Power-of-2 loops, no div/mod.
// ---------------------------------------------------------------------------
constexpr int VP = 36;  // vs channel pad (floats)

__global__ __launch_bounds__(256) void fir_kernel(const float* __restrict__ x) {
    __shared__ float vs[4 * 64 * VP];       // 36864 B
    const int i0 = blockIdx.x * 4, b = blockIdx.y;
    const int icc = blockIdx.z;
    const int c0 = icc << 5;
    const int tid = threadIdx.x;
    const float fw[4] = {0.125f, 0.375f, 0.375f, 0.125f};

    // --- vertical pass: unit (cg of 4 ch, w). 512 units, 2 per thread ---
    #pragma unroll
    for (int uu = 0; uu < 2; uu++) {
        const int u = tid + uu * 256;
        const int w = u & 63, cg = u >> 6;          // cg 0..7
        float R[4][7];
        #pragma unroll
        for (int j = 0; j < 4; j++) {
            const float* xp =
                x + ((size_t)(b * kC + c0 + cg * 4 + j) * kH) * kW + w;
            #pragma unroll
            for (int r = 0; r < 7; r++) {
                const int xr = i0 - 2 + r;
                R[j][r] = (xr >= 0 && xr < kH) ? xp[xr * kW] : 0.f;
            }
        }
        #pragma unroll
        for (int t = 0; t < 4; t++) {
            float4 v;
            v.x = fw[0]*R[0][t] + fw[1]*R[0][t+1] + fw[2]*R[0][t+2] + fw[3]*R[0][t+3];
            v.y = fw[0]*R[1][t] + fw[1]*R[1][t+1] + fw[2]*R[1][t+2] + fw[3]*R[1][t+3];
            v.z = fw[0]*R[2][t] + fw[1]*R[2][t+1] + fw[2]*R[2][t+2] + fw[3]*R[2][t+3];
            v.w = fw[0]*R[3][t] + fw[1]*R[3][t+1] + fw[2]*R[3][t+2] + fw[3]*R[3][t+3];
            *(float4*)&vs[(t * 64 + w) * VP + cg * 4] = v;
        }
    }
    __syncthreads();

    const __half* ub0 = g_u2 + (((size_t)b * 8 + icc) * kUH) * (kUW * CPH);

    auto emit = [&](int t, int wp, int cg) {
        const int i = i0 + t;
        if (i >= kUH) return;
        float4 acc = make_float4(0.f, 0.f, 0.f, 0.f);
        #pragma unroll
        for (int q = 0; q < 4; q++) {
            const int wq = wp - 2 + q;
            if (wq >= 0 && wq < kW) {
                const float4 v = *(const float4*)&vs[(t * 64 + wq) * VP + cg * 4];
                acc.x += fw[q] * v.x;
                acc.y += fw[q] * v.y;
                acc.z += fw[q] * v.z;
                acc.w += fw[q] * v.w;
            }
        }
        uint2 o;
        o.x = h2u(__floats2half2_rn(acc.x, acc.y));
        o.y = h2u(__floats2half2_rn(acc.z, acc.w));
        *(uint2*)((__half*)ub0 + ((size_t)i * kUW + wp) * CPH + cg * 4) = o;
    };

    // --- horizontal pass main: 2048 units, 8 exact iterations, no div ---
    #pragma unroll
    for (int j = 0; j < 8; j++) {
        const int idx = tid + j * 256;
        emit(idx >> 9, (idx >> 3) & 63, idx & 7);
    }
    // edge column wp = 64: 32 units
    if (tid < 32) emit(tid >> 3, 64, tid & 7);
}

// ---------------------------------------------------------------------------
// Weight transform: w[oc][ic][rs] -> g_wt2[rs][icc][oc][40] fp16
// ---------------------------------------------------------------------------
__global__ __launch_bounds__(256) void wt_kernel(const float* __restrict__ w) {
    __shared__ float sm[kC * 9];
    const int oc = blockIdx.x;
    for (int idx = threadIdx.x; idx < kC * 9; idx += 256)
        sm[idx] = w[(size_t)oc * kC * 9 + idx];
    __syncthreads();
    for (int idx = threadIdx.x; idx < kC * 9; idx += 256) {
        const int rs = idx >> 8, ic = idx & 255;
        const int icc = ic >> 5, ic32 = ic & 31;
        g_wt2[(((size_t)rs * 8 + icc) * kOC + oc) * CPH + ic32] =
            __float2half_rn(sm[ic * 9 + rs]);
    }
}

// ---------------------------------------------------------------------------
// Stage 2: implicit-GEMM conv, mma.sync fp16 + ldmatrix, bulk-copy pipeline.
// NEW: all LDSM first, early consumed-arrive (slot freed while MMAs run).
// CTA: M=128 x N=256, 16 warps = 4(M) x 4(N). 72 K-chunks. 128 CTAs. S=4.
// ---------------------------------------------------------------------------
__global__ __launch_bounds__(512, 1)
void conv_mma(const float* __restrict__ bias, float* __restrict__ y) {
    extern __shared__ __align__(16) char smem[];
    const int tid = threadIdx.x, wid = tid >> 5, lane = tid & 31;
    const uint32_t sb = smem_u32(smem);
    const uint32_t mbF = sb + MB_OFF;           // full[s]
    const uint32_t mbC = sb + MB_OFF + 8 * S;   // consumed[s]

    const int b = blockIdx.x >> 3, oh0 = (blockIdx.x & 7) << 2;
    const int wj = wid & 3;                 // m-subtile == oh row j
    const int wn0 = (wid >> 2) * 64;        // n-subtile

    if (tid == 0)
        for (int s = 0; s < S; s++) {
            mbar_init(mbF + 8 * s, 1);
            mbar_init(mbC + 8 * s, 16);
        }
    __syncthreads();

    auto issue = [&](int slot, int kc) {
        const int rs = kc >> 3, icc = kc & 7;
        const int r = rs / 3, s = rs % 3;
        const uint32_t mbar = mbF + 8 * slot;
        const uint32_t dst = sb + slot * SSZ;
        mbar_expect(mbar, SSZ);
        const __half* ub = g_u2 + (((size_t)b * 8 + icc) * kUH) * (kUW * CPH);
        #pragma unroll
        for (int j = 0; j < 4; j++) {
            const int h = 2 * (oh0 + j) + r;
            bulk_cp(dst + j * AROW,
                    ub + (size_t)h * (kUW * CPH) + s * CPH, AROW, mbar);
        }
        bulk_cp(dst + ASLOT,
                g_wt2 + (((size_t)rs * 8 + icc) * kOC) * CPH, BTILE, mbar);
    };

    if (tid == 0)
        for (int j = 0; j < S - 1; j++) issue(j, j);

    float acc[2][8][4];
    #pragma unroll
    for (int mt = 0; mt < 2; mt++)
        #pragma unroll
        for (int nt = 0; nt < 8; nt++)
            #pragma unroll
            for (int v = 0; v < 4; v++) acc[mt][nt][v] = 0.f;

    const uint32_t laneA = (lane & 15) * (2 * CPH * 2) + (lane >> 4) * 16;
    const uint32_t laneB = (lane & 15) * (CPH * 2) + (lane >> 4) * 16;

    for (int i = 0; i < KCH; i++) {
        // producer: issue chunk i+S-1 once slot's previous tenant is consumed
        if (wid == 0 && lane == 0) {
            const int j = i + S - 1;
            if (j < KCH) {
                if (i >= 1) mwait(mbC + 8 * ((i - 1) % S),
                                  (uint32_t)(((i - 1) / S) & 1));
                issue(j % S, j);
            }
        }

        mwait(mbF + 8 * (i % S), (uint32_t)((i / S) & 1));

        const uint32_t slotb = sb + (i % S) * SSZ;
        const uint32_t aBase = slotb + wj * AROW + laneA;
        const uint32_t bBase = slotb + ASLOT + wn0 * (CPH * 2) + laneB;

        // --- phase 1: ALL fragment loads (data -> registers) ---
        uint32_t af[2][2][4];     // [kk][mt][4]
        uint32_t bf[2][4][4];     // [kk][ntp][4]
        #pragma unroll
        for (int kk = 0; kk < 2; kk++) {
            ldsm4(aBase + kk * 32,
                  af[kk][0][0], af[kk][0][1], af[kk][0][2], af[kk][0][3]);
            ldsm4(aBase + 16 * (2 * CPH * 2) + kk * 32,
                  af[kk][1][0], af[kk][1][1], af[kk][1][2], af[kk][1][3]);
            #pragma unroll
            for (int ntp = 0; ntp < 4; ntp++)
                ldsm4(bBase + ntp * 16 * (CPH * 2) + kk * 32,
                      bf[kk][ntp][0], bf[kk][ntp][1],
                      bf[kk][ntp][2], bf[kk][ntp][3]);
        }
        // --- slot logically free: release-arrive consumed NOW ---
        __syncwarp();
        if (lane == 0) mbar_arrive(mbC + 8 * (i % S));

        // --- phase 2: all MMAs from registers ---
        #pragma unroll
        for (int kk = 0; kk < 2; kk++)
            #pragma unroll
            for (int ntp = 0; ntp < 4; ntp++) {
                mma_f16(acc[0][2 * ntp],     af[kk][0], bf[kk][ntp][0], bf[kk][ntp][2]);
                mma_f16(acc[0][2 * ntp + 1], af[kk][0], bf[kk][ntp][1], bf[kk][ntp][3]);
                mma_f16(acc[1][2 * ntp],     af[kk][1], bf[kk][ntp][0], bf[kk][ntp][2]);
                mma_f16(acc[1][2 * ntp + 1], af[kk][1], bf[kk][ntp][1], bf[kk][ntp][3]);
            }
    }

    // --- epilogue: transpose through smem for coalesced stores ---
    __syncthreads();
    float* st = (float*)smem;                         // [256 n][132 m]
    const int r0 = lane >> 2;
    const int c2 = (lane & 3) * 2;
    const int wm0 = wj * 32;
    #pragma unroll
    for (int mt = 0; mt < 2; mt++)
        #pragma unroll
        for (int nt = 0; nt < 8; nt++) {
            const int m = wm0 + mt * 16 + r0;
            const int n = wn0 + nt * 8 + c2;
            st[n * 132 + m]           = acc[mt][nt][0];
            st[(n + 1) * 132 + m]     = acc[mt][nt][1];
            st[n * 132 + m + 8]       = acc[mt][nt][2];
            st[(n + 1) * 132 + m + 8] = acc[mt][nt][3];
        }
    __syncthreads();

    const int row = tid >> 1, half = tid & 1;         // n-row (oc), m-half
    const float bv = __ldg(&bias[row]);
    const float* srow = st + row * 132 + half * 64;
    float* dst = y + ((size_t)(b * kOC + row)) * (kOH * kOW)
                   + oh0 * kOW + half * 64;
    #pragma unroll
    for (int t = 0; t < 16; t++) {
        float4 v = *(const float4*)(srow + t * 4);
        v.x += bv; v.y += bv; v.z += bv; v.w += bv;
        *(float4*)(dst + t * 4) = v;
    }
}

// ---------------------------------------------------------------------------
extern "C" void kernel_launch(void* const* d_in, const int* in_sizes, int n_in,
                              void* d_out, int out_size) {
    (void)in_sizes; (void)n_in; (void)out_size;
    const float* x    = (const float*)d_in[0];
    const float* w    = (const float*)d_in[1];
    const float* bias = (const float*)d_in[2];
    float* y = (float*)d_out;

    cudaFuncSetAttribute(conv_mma, cudaFuncAttributeMaxDynamicSharedMemorySize,
                         SMEM_TOT);

    fir_kernel<<<dim3(17, kB, 8), 256>>>(x);
    wt_kernel<<<kOC, 256>>>(w);
    conv_mma<<<kB * (kOH / 4), 512, SMEM_TOT>>>(bias, y);
}

// round 16
// speedup vs baseline: 7.3708x; 1.0553x over previous
#include <cuda_runtime.h>
#include <cuda_fp16.h>
#include <cstdint>

// ---------------------------------------------------------------------------
// Problem dims
// ---------------------------------------------------------------------------
constexpr int kB = 16, kC = 256, kH = 64, kW = 64;
constexpr int kUH = 65, kUW = 65;
constexpr int kOC = 256, kOH = 32, kOW = 32;

constexpr int KCH = 72;                 // 9 rs taps * 8 ic-chunks of 32
constexpr int S   = 3;                  // pipeline stages (2 CTAs/SM)
constexpr int CPH = 40;                 // padded channel stride (halves) = 80B
constexpr int AROW = 64 * CPH * 2;      // 5120 B: one trimmed (h) row in smem
constexpr int ASLOT = 4 * AROW;         // 20480
constexpr int BT2  = 128 * CPH * 2;     // 10240 B: half-oc B tile
constexpr int SSZ  = ASLOT + BT2;       // 30720
constexpr int MB_OFF = S * SSZ;         // 92160: full[S] then consumed[S]
constexpr int SMEM_TOT = MB_OFF + 128;  // per-CTA; 2 CTAs = 184.6 KB/SM

// Scratch (fp16, pre-padded):
// g_u2[b][icc(8)][h(65)][w(65)][40]   g_wt2[rs(9)][icc(8)][oc(256)][40]
__device__ __align__(1024) __half g_u2[(size_t)kB * 8 * kUH * kUW * CPH];
__device__ __align__(1024) __half g_wt2[9 * 8 * kOC * CPH];

// ---------------------------------------------------------------------------
// Helpers
// ---------------------------------------------------------------------------
__device__ __forceinline__ uint32_t smem_u32(const void* p) {
    uint32_t a;
    asm("{ .reg .u64 t; cvta.to.shared.u64 t, %1; cvt.u32.u64 %0, t; }"
        : "=r"(a) : "l"(p));
    return a;
}
__device__ __forceinline__ uint32_t h2u(__half2 h) {
    return *reinterpret_cast<const uint32_t*>(&h);
}
__device__ __forceinline__ void mbar_init(uint32_t a, uint32_t cnt) {
    asm volatile("mbarrier.init.shared.b64 [%0], %1;" :: "r"(a), "r"(cnt) : "memory");
}
__device__ __forceinline__ void mbar_expect(uint32_t a, uint32_t bytes) {
    asm volatile("mbarrier.arrive.expect_tx.shared.b64 _, [%0], %1;"
                 :: "r"(a), "r"(bytes) : "memory");
}
__device__ __forceinline__ void mbar_arrive(uint32_t a) {
    asm volatile("mbarrier.arrive.release.cta.shared::cta.b64 _, [%0];"
                 :: "r"(a) : "memory");
}
__device__ __forceinline__ void mwait(uint32_t mbar, uint32_t ph) {
    asm volatile(
        "{\n\t.reg .pred P;\n"
        "W%=:\n\tmbarrier.try_wait.parity.acquire.cta.shared::cta.b64 P, [%0], %1, 0x989680;\n\t"
        "@P bra D%=;\n\tbra W%=;\n"
        "D%=:\n\t}"
        :: "r"(mbar), "r"(ph) : "memory");
}
__device__ __forceinline__ void bulk_cp(uint32_t dst, const void* src,
                                        uint32_t bytes, uint32_t mbar) {
    asm volatile(
        "cp.async.bulk.shared::cta.global.mbarrier::complete_tx::bytes "
        "[%0], [%1], %2, [%3];"
        :: "r"(dst), "l"(src), "r"(bytes), "r"(mbar) : "memory");
}
__device__ __forceinline__ void ldsm4(uint32_t addr, uint32_t& r0, uint32_t& r1,
                                      uint32_t& r2, uint32_t& r3) {
    asm volatile("ldmatrix.sync.aligned.m8n8.x4.shared.b16 {%0,%1,%2,%3}, [%4];"
                 : "=r"(r0), "=r"(r1), "=r"(r2), "=r"(r3) : "r"(addr));
}
__device__ __forceinline__ void mma_f16(float* d, const uint32_t* a,
                                        uint32_t b0, uint32_t b1) {
    asm volatile(
        "mma.sync.aligned.m16n8k16.row.col.f32.f16.f16.f32 "
        "{%0,%1,%2,%3}, {%4,%5,%6,%7}, {%8,%9}, {%0,%1,%2,%3};"
        : "+f"(d[0]), "+f"(d[1]), "+f"(d[2]), "+f"(d[3])
        : "r"(a[0]), "r"(a[1]), "r"(a[2]), "r"(a[3]), "r"(b0), "r"(b1));
}

// ---------------------------------------------------------------------------
// Stage 1: fir (z<8) + weight transform (z==8) in one launch.
// fir: separable 4x4 FIR, 4 output rows / block, 32-channel chunk per block.
// ---------------------------------------------------------------------------
constexpr int VP = 36;  // vs channel pad (floats)

__global__ __launch_bounds__(256)
void fir_wt_kernel(const float* __restrict__ x, const float* __restrict__ w) {
    __shared__ float vs[4 * 64 * VP];       // 36864 B (wt path reuses 9216 B)
    const int tid = threadIdx.x;

    if (blockIdx.z == 8) {
        // ---- weight transform: block -> one oc ----
        const int idx2 = blockIdx.y * 17 + blockIdx.x;
        if (idx2 >= kOC) return;
        const int oc = idx2;
        float* sm = vs;
        for (int idx = tid; idx < kC * 9; idx += 256)
            sm[idx] = w[(size_t)oc * kC * 9 + idx];
        __syncthreads();
        for (int idx = tid; idx < kC * 9; idx += 256) {
            const int rs = idx >> 8, ic = idx & 255;
            const int icc = ic >> 5, ic32 = ic & 31;
            g_wt2[(((size_t)rs * 8 + icc) * kOC + oc) * CPH + ic32] =
                __float2half_rn(sm[ic * 9 + rs]);
        }
        return;
    }

    const int i0 = blockIdx.x * 4, b = blockIdx.y;
    const int icc = blockIdx.z;
    const int c0 = icc << 5;
    const float fw[4] = {0.125f, 0.375f, 0.375f, 0.125f};

    // --- vertical pass: unit (cg of 4 ch, w). 512 units, 2 per thread ---
    #pragma unroll
    for (int uu = 0; uu < 2; uu++) {
        const int u = tid + uu * 256;
        const int ww = u & 63, cg = u >> 6;          // cg 0..7
        float R[4][7];
        #pragma unroll
        for (int j = 0; j < 4; j++) {
            const float* xp =
                x + ((size_t)(b * kC + c0 + cg * 4 + j) * kH) * kW + ww;
            #pragma unroll
            for (int r = 0; r < 7; r++) {
                const int xr = i0 - 2 + r;
                R[j][r] = (xr >= 0 && xr < kH) ? xp[xr * kW] : 0.f;
            }
        }
        #pragma unroll
        for (int t = 0; t < 4; t++) {
            float4 v;
            v.x = fw[0]*R[0][t] + fw[1]*R[0][t+1] + fw[2]*R[0][t+2] + fw[3]*R[0][t+3];
            v.y = fw[0]*R[1][t] + fw[1]*R[1][t+1] + fw[2]*R[1][t+2] + fw[3]*R[1][t+3];
            v.z = fw[0]*R[2][t] + fw[1]*R[2][t+1] + fw[2]*R[2][t+2] + fw[3]*R[2][t+3];
            v.w = fw[0]*R[3][t] + fw[1]*R[3][t+1] + fw[2]*R[3][t+2] + fw[3]*R[3][t+3];
            *(float4*)&vs[(t * 64 + ww) * VP + cg * 4] = v;
        }
    }
    __syncthreads();

    const __half* ub0 = g_u2 + (((size_t)b * 8 + icc) * kUH) * (kUW * CPH);

    auto emit = [&](int t, int wp, int cg) {
        const int i = i0 + t;
        if (i >= kUH) return;
        float4 acc = make_float4(0.f, 0.f, 0.f, 0.f);
        #pragma unroll
        for (int q = 0; q < 4; q++) {
            const int wq = wp - 2 + q;
            if (wq >= 0 && wq < kW) {
                const float4 v = *(const float4*)&vs[(t * 64 + wq) * VP + cg * 4];
                acc.x += fw[q] * v.x;
                acc.y += fw[q] * v.y;
                acc.z += fw[q] * v.z;
                acc.w += fw[q] * v.w;
            }
        }
        uint2 o;
        o.x = h2u(__floats2half2_rn(acc.x, acc.y));
        o.y = h2u(__floats2half2_rn(acc.z, acc.w));
        *(uint2*)((__half*)ub0 + ((size_t)i * kUW + wp) * CPH + cg * 4) = o;
    };

    #pragma unroll
    for (int j = 0; j < 8; j++) {
        const int idx = tid + j * 256;
        emit(idx >> 9, (idx >> 3) & 63, idx & 7);
    }
    if (tid < 32) emit(tid >> 3, 64, tid & 7);
}

// ---------------------------------------------------------------------------
// Stage 2 (v2): implicit-GEMM conv, mma.sync fp16 + ldmatrix, bulk-copy
// pipeline. CTA tile M=128 x N=128, 256 threads (8 warps = 4M x 2N),
// 256 CTAs -> 2 CTAs/SM so one CTA's stalls hide behind the other's MMAs.
// ---------------------------------------------------------------------------
__global__ __launch_bounds__(256, 2)
void conv_mma(const float* __restrict__ bias, float* __restrict__ y) {
    extern __shared__ __align__(16) char smem[];
    const int tid = threadIdx.x, wid = tid >> 5, lane = tid & 31;
    const uint32_t sb = smem_u32(smem);
    const uint32_t mbF = sb + MB_OFF;           // full[s]
    const uint32_t mbC = sb + MB_OFF + 8 * S;   // consumed[s]

    const int ntile = blockIdx.x & 1;
    const int oh0 = ((blockIdx.x >> 1) & 7) << 2;
    const int b = blockIdx.x >> 4;
    const int oc0 = ntile << 7;
    const int wj = wid & 3;                 // m-subtile == oh row j
    const int wn0 = (wid >> 2) * 64;        // n-subtile (0 or 64)

    if (tid == 0)
        for (int s = 0; s < S; s++) {
            mbar_init(mbF + 8 * s, 1);
            mbar_init(mbC + 8 * s, 8);
        }
    __syncthreads();

    auto issue = [&](int slot, int kc) {
        const int rs = kc >> 3, icc = kc & 7;
        const int r = rs / 3, s = rs % 3;
        const uint32_t mbar = mbF + 8 * slot;
        const uint32_t dst = sb + slot * SSZ;
        mbar_expect(mbar, SSZ);
        const __half* ub = g_u2 + (((size_t)b * 8 + icc) * kUH) * (kUW * CPH);
        #pragma unroll
        for (int j = 0; j < 4; j++) {
            const int h = 2 * (oh0 + j) + r;
            bulk_cp(dst + j * AROW,
                    ub + (size_t)h * (kUW * CPH) + s * CPH, AROW, mbar);
        }
        bulk_cp(dst + ASLOT,
                g_wt2 + (((size_t)rs * 8 + icc) * kOC + oc0) * CPH, BT2, mbar);
    };

    if (tid == 0)
        for (int j = 0; j < S - 1; j++) issue(j, j);

    float acc[2][8][4];
    #pragma unroll
    for (int mt = 0; mt < 2; mt++)
        #pragma unroll
        for (int nt = 0; nt < 8; nt++)
            #pragma unroll
            for (int v = 0; v < 4; v++) acc[mt][nt][v] = 0.f;

    const uint32_t laneA = (lane & 15) * (2 * CPH * 2) + (lane >> 4) * 16;
    const uint32_t laneB = (lane & 15) * (CPH * 2) + (lane >> 4) * 16;

    for (int i = 0; i < KCH; i++) {
        if (tid == 0) {
            const int j = i + S - 1;
            if (j < KCH) {
                if (i >= 1) mwait(mbC + 8 * ((i - 1) % S),
                                  (uint32_t)(((i - 1) / S) & 1));
                issue(j % S, j);
            }
        }

        mwait(mbF + 8 * (i % S), (uint32_t)((i / S) & 1));

        const uint32_t slotb = sb + (i % S) * SSZ;
        const uint32_t aBase = slotb + wj * AROW + laneA;
        const uint32_t bBase = slotb + ASLOT + wn0 * (CPH * 2) + laneB;

        #pragma unroll
        for (int kk = 0; kk < 2; kk++) {          // 2 x k16
            uint32_t a[2][4];
            ldsm4(aBase + kk * 32, a[0][0], a[0][1], a[0][2], a[0][3]);
            ldsm4(aBase + 16 * (2 * CPH * 2) + kk * 32,
                  a[1][0], a[1][1], a[1][2], a[1][3]);
            #pragma unroll
            for (int ntp = 0; ntp < 4; ntp++) {
                uint32_t b0, b1, b2, b3;
                ldsm4(bBase + ntp * 16 * (CPH * 2) + kk * 32, b0, b1, b2, b3);
                mma_f16(acc[0][2 * ntp],     a[0], b0, b2);
                mma_f16(acc[0][2 * ntp + 1], a[0], b1, b3);
                mma_f16(acc[1][2 * ntp],     a[1], b0, b2);
                mma_f16(acc[1][2 * ntp + 1], a[1], b1, b3);
            }
        }
        __syncwarp();
        if (lane == 0) mbar_arrive(mbC + 8 * (i % S));
    }

    // --- epilogue: transpose through smem for coalesced stores ---
    __syncthreads();
    float* st = (float*)smem;                         // [128 n][132 m]
    const int r0 = lane >> 2;
    const int c2 = (lane & 3) * 2;
    const int wm0 = wj * 32;
    #pragma unroll
    for (int mt = 0; mt < 2; mt++)
        #pragma unroll
        for (int nt = 0; nt < 8; nt++) {
            const int m = wm0 + mt * 16 + r0;
            const int n = wn0 + nt * 8 + c2;
            st[n * 132 + m]           = acc[mt][nt][0];
            st[(n + 1) * 132 + m]     = acc[mt][nt][1];
            st[n * 132 + m + 8]       = acc[mt][nt][2];
            st[(n + 1) * 132 + m + 8] = acc[mt][nt][3];
        }
    __syncthreads();

    const int row = tid >> 1, half = tid & 1;         // n-row within tile
    const float bv = __ldg(&bias[oc0 + row]);
    const float* srow = st + row * 132 + half * 64;
    float* dst = y + ((size_t)(b * kOC + oc0 + row)) * (kOH * kOW)
                   + oh0 * kOW + half * 64;
    #pragma unroll
    for (int t = 0; t < 16; t++) {
        float4 v = *(const float4*)(srow + t * 4);
        v.x += bv; v.y += bv; v.z += bv; v.w += bv;
        *(float4*)(dst + t * 4) = v;
    }
}

// ---------------------------------------------------------------------------
extern "C" void kernel_launch(void* const* d_in, const int* in_sizes, int n_in,
                              void* d_out, int out_size) {
    (void)in_sizes; (void)n_in; (void)out_size;
    const float* x    = (const float*)d_in[0];
    const float* w    = (const float*)d_in[1];
    const float* bias = (const float*)d_in[2];
    float* y = (float*)d_out;

    cudaFuncSetAttribute(conv_mma, cudaFuncAttributeMaxDynamicSharedMemorySize,
                         SMEM_TOT);

    fir_wt_kernel<<<dim3(17, kB, 9), 256>>>(x, w);
    conv_mma<<<kB * (kOH / 4) * 2, 256, SMEM_TOT>>>(bias, y);
}